// round 6
// baseline (speedup 1.0000x reference)
#include <cuda_runtime.h>
#include <cuda_bf16.h>

#define N_NODES 50000
#define N_EDGES 800000
#define D 128
#define BM 64
#define KC 32
#define SSTRIDE 36   // even (8B-aligned k-pairs), 36*4%16==0 (STS.128-aligned rows)

typedef unsigned long long ull;

__device__ __forceinline__ ull ffma2(ull a, ull b, ull c) {
    ull d;
    asm("fma.rn.f32x2 %0, %1, %2, %3;" : "=l"(d) : "l"(a), "l"(b), "l"(c));
    return d;
}
__device__ __forceinline__ float2 unpack2(ull v) {
    float2 f;
    asm("mov.b64 {%0, %1}, %2;" : "=f"(f.x), "=f"(f.y) : "l"(v));
    return f;
}

// ---------------- scratch (device globals; 16B-aligned) ----------------------
__device__ __align__(16) int   g_deg[N_NODES];
__device__ __align__(16) int   g_off[N_NODES + 1];
__device__ __align__(16) int   g_cur[N_NODES];
__device__ __align__(16) int   g_ssrc[N_EDGES];
__device__ __align__(16) float g_agg[(size_t)N_NODES * D];   // mean-agg of x
__device__ __align__(16) float g_h[(size_t)N_NODES * D];     // relu(layer1)
__device__ __align__(16) float g_y2[(size_t)N_NODES * 2];    // h @ W2_l^T

// ---------------- prep: degree histogram, scan, binning ----------------------
__global__ void k_zero_deg() {
    int i = blockIdx.x * blockDim.x + threadIdx.x;
    if (i < N_NODES) g_deg[i] = 0;
}

__global__ void k_hist(const int* __restrict__ ei) {
    int e = blockIdx.x * blockDim.x + threadIdx.x;
    if (e < N_EDGES) {
        int dst = ei[N_EDGES + e];
        if ((unsigned)dst < (unsigned)N_NODES) atomicAdd(&g_deg[dst], 1);
    }
}

__global__ void k_scan() {
    __shared__ int sums[1024];
    int t = threadIdx.x;
    const int CH = (N_NODES + 1023) / 1024;   // 49
    int begin = t * CH;
    int end = begin + CH; if (end > N_NODES) end = N_NODES;
    int s = 0;
    for (int i = begin; i < end; ++i) s += g_deg[i];
    sums[t] = s;
    __syncthreads();
    for (int off = 1; off < 1024; off <<= 1) {
        int v = (t >= off) ? sums[t - off] : 0;
        __syncthreads();
        if (t >= off) sums[t] += v;
        __syncthreads();
    }
    int base = (t == 0) ? 0 : sums[t - 1];
    for (int i = begin; i < end; ++i) {
        g_off[i] = base;
        g_cur[i] = base;
        base += g_deg[i];
    }
    if (t == 1023) g_off[N_NODES] = sums[1023];
}

__global__ void k_bin(const int* __restrict__ ei) {
    int e = blockIdx.x * blockDim.x + threadIdx.x;
    if (e < N_EDGES) {
        int src = ei[e];
        int dst = ei[N_EDGES + e];
        if ((unsigned)dst < (unsigned)N_NODES && (unsigned)src < (unsigned)N_NODES) {
            int p = atomicAdd(&g_cur[dst], 1);
            if ((unsigned)p < (unsigned)N_EDGES) g_ssrc[p] = src;
        }
    }
}

// ---------------- layer-1 aggregation: one warp per node ---------------------
__global__ void k_agg1(const float* __restrict__ x) {
    int w = (blockIdx.x * blockDim.x + threadIdx.x) >> 5;
    int lane = threadIdx.x & 31;
    if (w >= N_NODES) return;
    int beg = g_off[w], end = g_off[w + 1];
    float4 acc = make_float4(0.f, 0.f, 0.f, 0.f);
    const float4* xv = (const float4*)x;
    for (int e = beg; e < end; ++e) {
        int s = g_ssrc[e];
        float4 v = xv[(size_t)s * 32 + lane];
        acc.x += v.x; acc.y += v.y; acc.z += v.z; acc.w += v.w;
    }
    float inv = 1.0f / fmaxf((float)(end - beg), 1.0f);
    float4* o = (float4*)g_agg;
    o[(size_t)w * 32 + lane] = make_float4(acc.x * inv, acc.y * inv, acc.z * inv, acc.w * inv);
}

// ---------------- layer-1 GEMM: h = relu([agg|x] @ [Wl|Wr]^T + b1) -----------
// Packed-f32x2, 64x128 tile, 4x8 per thread: acc2 = 64 regs (no spills).
__global__ void __launch_bounds__(256, 2) k_gemm1(
    const float* __restrict__ x,
    const float* __restrict__ Wl, const float* __restrict__ Wr,
    const float* __restrict__ b1)
{
    __shared__ float sA[BM * SSTRIDE];   // input rows (nodes): 64 x 32
    __shared__ float sB[128 * SSTRIDE];  // weight rows (outputs): 128 x 32
    const int tid = threadIdx.x;
    const int m0 = blockIdx.x * BM;
    const int tm = tid >> 4;             // 0..15
    const int tj = tid & 15;             // 0..15

    ull acc2[4][8];
#pragma unroll
    for (int i = 0; i < 4; ++i)
#pragma unroll
        for (int j = 0; j < 8; ++j) acc2[i][j] = 0ull;

    for (int kc = 0; kc < 256; kc += KC) {
        const bool left = (kc < 128);
        const int klocal = left ? kc : (kc - 128);
        // stage input tile: 64 rows x 8 float4 = 512 float4
#pragma unroll
        for (int it = 0; it < 2; ++it) {
            int q = tid + it * 256;
            int row = q >> 3, c4 = q & 7;
            int node = m0 + row;
            float4 v = make_float4(0.f, 0.f, 0.f, 0.f);
            if (node < N_NODES) {
                const float* srcp = left ? (g_agg + (size_t)node * D)
                                         : (x + (size_t)node * D);
                v = *(const float4*)(srcp + klocal + c4 * 4);
            }
            *(float4*)(sA + row * SSTRIDE + c4 * 4) = v;
        }
        // stage weight tile: 128 rows x 8 float4 = 1024 float4
#pragma unroll
        for (int it = 0; it < 4; ++it) {
            int q = tid + it * 256;
            int row = q >> 3, c4 = q & 7;
            const float* srcp = left ? (Wl + row * D) : (Wr + row * D);
            float4 v = *(const float4*)(srcp + klocal + c4 * 4);
            *(float4*)(sB + row * SSTRIDE + c4 * 4) = v;
        }
        __syncthreads();

#pragma unroll 4
        for (int k2 = 0; k2 < KC / 2; ++k2) {
            ull a2[4], w2[8];
#pragma unroll
            for (int i = 0; i < 4; ++i)
                a2[i] = ((const ull*)(sA + (tm + 16 * i) * SSTRIDE))[k2];
#pragma unroll
            for (int j = 0; j < 8; ++j)
                w2[j] = ((const ull*)(sB + (tj + 16 * j) * SSTRIDE))[k2];
#pragma unroll
            for (int i = 0; i < 4; ++i)
#pragma unroll
                for (int j = 0; j < 8; ++j)
                    acc2[i][j] = ffma2(a2[i], w2[j], acc2[i][j]);
        }
        __syncthreads();
    }

    float bias[8];
#pragma unroll
    for (int j = 0; j < 8; ++j) bias[j] = b1[tj + 16 * j];

#pragma unroll
    for (int i = 0; i < 4; ++i) {
        int node = m0 + tm + 16 * i;
        if (node < N_NODES) {
            float* hp = g_h + (size_t)node * D;
#pragma unroll
            for (int j = 0; j < 8; ++j) {
                float2 p = unpack2(acc2[i][j]);
                float v = p.x + p.y + bias[j];
                hp[tj + 16 * j] = fmaxf(v, 0.f);
            }
        }
    }
}

// ---------------- layer-2: y2 = h@W2_l^T ; out = h@W2_r^T + b2 ---------------
__global__ void k_l2self(const float* __restrict__ W2l,
                         const float* __restrict__ W2r,
                         const float* __restrict__ b2,
                         float* __restrict__ out)
{
    int v = (blockIdx.x * blockDim.x + threadIdx.x) >> 5;
    int lane = threadIdx.x & 31;
    if (v >= N_NODES) return;
    float4 hh = ((const float4*)(g_h + (size_t)v * D))[lane];
    float4 a = ((const float4*)W2l)[lane];            // row 0
    float4 b = ((const float4*)(W2l + D))[lane];      // row 1
    float4 c = ((const float4*)W2r)[lane];
    float4 d = ((const float4*)(W2r + D))[lane];
    float d0 = hh.x * a.x + hh.y * a.y + hh.z * a.z + hh.w * a.w;
    float d1 = hh.x * b.x + hh.y * b.y + hh.z * b.z + hh.w * b.w;
    float d2 = hh.x * c.x + hh.y * c.y + hh.z * c.z + hh.w * c.w;
    float d3 = hh.x * d.x + hh.y * d.y + hh.z * d.z + hh.w * d.w;
#pragma unroll
    for (int o = 16; o > 0; o >>= 1) {
        d0 += __shfl_xor_sync(0xFFFFFFFFu, d0, o);
        d1 += __shfl_xor_sync(0xFFFFFFFFu, d1, o);
        d2 += __shfl_xor_sync(0xFFFFFFFFu, d2, o);
        d3 += __shfl_xor_sync(0xFFFFFFFFu, d3, o);
    }
    if (lane == 0) {
        g_y2[v * 2 + 0] = d0;
        g_y2[v * 2 + 1] = d1;
        out[v * 2 + 0] = d2 + b2[0];
        out[v * 2 + 1] = d3 + b2[1];
    }
}

// ---------------- layer-2 aggregation of y2 (8 bytes/edge) -------------------
__global__ void k_agg2(float* __restrict__ out) {
    int v = (blockIdx.x * blockDim.x + threadIdx.x) >> 5;
    int lane = threadIdx.x & 31;
    if (v >= N_NODES) return;
    int beg = g_off[v], end = g_off[v + 1];
    float a0 = 0.f, a1 = 0.f;
    for (int e = beg + lane; e < end; e += 32) {
        int s = g_ssrc[e];
        float2 y = ((const float2*)g_y2)[s];
        a0 += y.x; a1 += y.y;
    }
#pragma unroll
    for (int o = 16; o > 0; o >>= 1) {
        a0 += __shfl_xor_sync(0xFFFFFFFFu, a0, o);
        a1 += __shfl_xor_sync(0xFFFFFFFFu, a1, o);
    }
    if (lane == 0) {
        float inv = 1.0f / fmaxf((float)(end - beg), 1.0f);
        out[v * 2 + 0] += a0 * inv;
        out[v * 2 + 1] += a1 * inv;
    }
}

// ---------------- launch ------------------------------------------------------
extern "C" void kernel_launch(void* const* d_in, const int* in_sizes, int n_in,
                              void* d_out, int out_size)
{
    const float* x    = (const float*)d_in[0];
    const int*   ei   = (const int*)d_in[1];     // JAX default: int64 demoted to int32
    const float* W1l  = (const float*)d_in[2];
    const float* W1r  = (const float*)d_in[3];
    const float* b1   = (const float*)d_in[4];
    const float* W2l  = (const float*)d_in[5];
    const float* W2r  = (const float*)d_in[6];
    const float* b2   = (const float*)d_in[7];
    float* out = (float*)d_out;

    k_zero_deg<<<(N_NODES + 255) / 256, 256>>>();
    k_hist<<<N_EDGES / 256, 256>>>(ei);
    k_scan<<<1, 1024>>>();
    k_bin<<<N_EDGES / 256, 256>>>(ei);
    k_agg1<<<(N_NODES * 32 + 255) / 256, 256>>>(x);
    k_gemm1<<<(N_NODES + BM - 1) / BM, 256>>>(x, W1l, W1r, b1);
    k_l2self<<<(N_NODES * 32 + 255) / 256, 256>>>(W2l, W2r, b2, out);
    k_agg2<<<(N_NODES * 32 + 255) / 256, 256>>>(out);
}

// round 8
// speedup vs baseline: 1.3142x; 1.3142x over previous
#include <cuda_runtime.h>
#include <cuda_bf16.h>
#include <cstdint>

#define N_NODES 50000
#define N_EDGES 800000
#define D 128

// ================= scratch =====================================================
__device__ __align__(16) int   g_deg[N_NODES];
__device__ __align__(16) int   g_off[N_NODES + 1];
__device__ __align__(16) int   g_cur[N_NODES];
__device__ __align__(16) int   g_ssrc[N_EDGES];
__device__ __align__(16) float g_agg[(size_t)N_NODES * D];   // mean-agg of x
__device__ __align__(16) float g_y2[(size_t)N_NODES * 2];    // h @ W2_l^T
__device__ __align__(16) __nv_bfloat16 g_w1hi[128 * 256];    // [Wl|Wr] hi split
__device__ __align__(16) __nv_bfloat16 g_w1lo[128 * 256];    // [Wl|Wr] lo split

// ================= helpers =====================================================
__device__ __forceinline__ uint32_t smem_u32(const void* p) {
    uint32_t a;
    asm("{ .reg .u64 t; cvta.to.shared.u64 t, %1; cvt.u32.u64 %0, t; }"
        : "=r"(a) : "l"(p));
    return a;
}

__device__ __forceinline__ void ldmx4(uint32_t* r, uint32_t addr) {
    asm volatile("ldmatrix.sync.aligned.m8n8.x4.shared.b16 {%0,%1,%2,%3}, [%4];"
        : "=r"(r[0]), "=r"(r[1]), "=r"(r[2]), "=r"(r[3]) : "r"(addr));
}

__device__ __forceinline__ void mma16816(float* d, const uint32_t* a,
                                         uint32_t b0, uint32_t b1) {
    asm volatile("mma.sync.aligned.m16n8k16.row.col.f32.bf16.bf16.f32 "
        "{%0,%1,%2,%3}, {%4,%5,%6,%7}, {%8,%9}, {%0,%1,%2,%3};"
        : "+f"(d[0]), "+f"(d[1]), "+f"(d[2]), "+f"(d[3])
        : "r"(a[0]), "r"(a[1]), "r"(a[2]), "r"(a[3]), "r"(b0), "r"(b1));
}

// split 8 fp32 -> packed bf16 hi (uint4) and lo residual (uint4)
__device__ __forceinline__ void split8(float4 u, float4 w, uint4& hv, uint4& lv) {
    float f[8] = {u.x, u.y, u.z, u.w, w.x, w.y, w.z, w.w};
    uint32_t hi[8], lo[8];
#pragma unroll
    for (int t = 0; t < 8; ++t) {
        __nv_bfloat16 h = __float2bfloat16(f[t]);
        hi[t] = (uint32_t)__bfloat16_as_ushort(h);
        lo[t] = (uint32_t)__bfloat16_as_ushort(__float2bfloat16(f[t] - __bfloat162float(h)));
    }
    hv = make_uint4(hi[0] | (hi[1] << 16), hi[2] | (hi[3] << 16),
                    hi[4] | (hi[5] << 16), hi[6] | (hi[7] << 16));
    lv = make_uint4(lo[0] | (lo[1] << 16), lo[2] | (lo[3] << 16),
                    lo[4] | (lo[5] << 16), lo[6] | (lo[7] << 16));
}

// ================= prep kernels ================================================
__global__ void k_zero_deg() {
    int i = blockIdx.x * blockDim.x + threadIdx.x;
    if (i < N_NODES) g_deg[i] = 0;
}

__global__ void k_hist(const int* __restrict__ ei) {
    int e = blockIdx.x * blockDim.x + threadIdx.x;
    if (e < N_EDGES) {
        int dst = ei[N_EDGES + e];
        if ((unsigned)dst < (unsigned)N_NODES) atomicAdd(&g_deg[dst], 1);
    }
}

__global__ void k_scan() {
    __shared__ int sums[1024];
    int t = threadIdx.x;
    const int CH = (N_NODES + 1023) / 1024;
    int begin = t * CH;
    int end = begin + CH; if (end > N_NODES) end = N_NODES;
    int s = 0;
    for (int i = begin; i < end; ++i) s += g_deg[i];
    sums[t] = s;
    __syncthreads();
    for (int off = 1; off < 1024; off <<= 1) {
        int v = (t >= off) ? sums[t - off] : 0;
        __syncthreads();
        if (t >= off) sums[t] += v;
        __syncthreads();
    }
    int base = (t == 0) ? 0 : sums[t - 1];
    for (int i = begin; i < end; ++i) {
        g_off[i] = base;
        g_cur[i] = base;
        base += g_deg[i];
    }
    if (t == 1023) g_off[N_NODES] = sums[1023];
}

__global__ void k_bin(const int* __restrict__ ei) {
    int e = blockIdx.x * blockDim.x + threadIdx.x;
    if (e < N_EDGES) {
        int src = ei[e];
        int dst = ei[N_EDGES + e];
        if ((unsigned)dst < (unsigned)N_NODES && (unsigned)src < (unsigned)N_NODES) {
            int p = atomicAdd(&g_cur[dst], 1);
            if ((unsigned)p < (unsigned)N_EDGES) g_ssrc[p] = src;
        }
    }
}

// ================= layer-1 aggregation (unchanged) =============================
__global__ void k_agg1(const float* __restrict__ x) {
    int w = (blockIdx.x * blockDim.x + threadIdx.x) >> 5;
    int lane = threadIdx.x & 31;
    if (w >= N_NODES) return;
    int beg = g_off[w], end = g_off[w + 1];
    float4 acc = make_float4(0.f, 0.f, 0.f, 0.f);
    const float4* xv = (const float4*)x;
    for (int e = beg; e < end; ++e) {
        int s = g_ssrc[e];
        float4 v = xv[(size_t)s * 32 + lane];
        acc.x += v.x; acc.y += v.y; acc.z += v.z; acc.w += v.w;
    }
    float inv = 1.0f / fmaxf((float)(end - beg), 1.0f);
    float4* o = (float4*)g_agg;
    o[(size_t)w * 32 + lane] = make_float4(acc.x * inv, acc.y * inv, acc.z * inv, acc.w * inv);
}

// ================= weight split prep: Wcat -> bf16 hi/lo =======================
__global__ void k_prep_w(const float* __restrict__ Wl, const float* __restrict__ Wr) {
    int j = blockIdx.x;        // 0..127
    int k = threadIdx.x;       // 0..255
    float v = (k < 128) ? Wl[j * 128 + k] : Wr[j * 128 + (k - 128)];
    __nv_bfloat16 h = __float2bfloat16(v);
    float resid = v - __bfloat162float(h);
    g_w1hi[j * 256 + k] = h;
    g_w1lo[j * 256 + k] = __float2bfloat16(resid);
}

// ================= fused layer1 GEMM (warp mma) + layer2 self ==================
// Per block: 128 nodes x 128 outputs. K=256 in 4 chunks of 64.
// bf16 split, 3 mma passes (hi*hi + hi*lo + lo*hi).
// smem tiles: rows padded to 72 bf16 (144B): ldmatrix row addrs conflict-free.
#define TSTRIDE 72            // bf16 elements per row (144 bytes)
#define TBYTES  (128 * TSTRIDE * 2)   // 18432 per tile

__global__ void __launch_bounds__(256, 2) k_gemm_mma(
    const float* __restrict__ x,
    const float* __restrict__ b1g,
    const float* __restrict__ W2l, const float* __restrict__ W2r,
    const float* __restrict__ b2,
    float* __restrict__ out)
{
    extern __shared__ char dynsm[];
    char* sAhi = dynsm;
    char* sAlo = dynsm + TBYTES;
    char* sBhi = dynsm + 2 * TBYTES;
    char* sBlo = dynsm + 3 * TBYTES;
    __shared__ float s_b1[128];
    __shared__ float s_w2[4][128];

    const int tid = threadIdx.x;
    const int w = tid >> 5;
    const int lane = tid & 31;
    const int m0 = blockIdx.x * 128;

    if (tid < 128) {
        s_b1[tid] = b1g[tid];
        s_w2[0][tid] = W2l[tid];
        s_w2[1][tid] = W2l[128 + tid];
        s_w2[2][tid] = W2r[tid];
        s_w2[3][tid] = W2r[128 + tid];
    }

    const uint32_t uAhi = smem_u32(sAhi), uAlo = smem_u32(sAlo);
    const uint32_t uBhi = smem_u32(sBhi), uBlo = smem_u32(sBlo);

    float acc[16][4];
#pragma unroll
    for (int j = 0; j < 16; ++j)
#pragma unroll
        for (int q = 0; q < 4; ++q) acc[j][q] = 0.f;

    const int srow = tid >> 1;          // staging row 0..127
    const int shalf = tid & 1;          // 0/1 -> 32-element half

    for (int c = 0; c < 4; ++c) {
        if (c) __syncthreads();         // previous chunk's mma reads done
        // ---- stage A: fp32 -> bf16 hi/lo, 32 elems per thread
        {
            int node = m0 + srow;
            bool valid = node < N_NODES;
            const float* basep = (c < 2) ? g_agg : x;
            const float* srcp = basep + (size_t)(valid ? node : 0) * D
                                + (c & 1) * 64 + shalf * 32;
            char* dsth = sAhi + srow * 144 + shalf * 64;
            char* dstl = sAlo + srow * 144 + shalf * 64;
#pragma unroll
            for (int i = 0; i < 4; ++i) {
                float4 u = make_float4(0.f, 0.f, 0.f, 0.f);
                float4 v = make_float4(0.f, 0.f, 0.f, 0.f);
                if (valid) {
                    u = *(const float4*)(srcp + i * 8);
                    v = *(const float4*)(srcp + i * 8 + 4);
                }
                uint4 hv, lv;
                split8(u, v, hv, lv);
                *(uint4*)(dsth + i * 16) = hv;
                *(uint4*)(dstl + i * 16) = lv;
            }
        }
        // ---- stage B: copy pre-split bf16 weights
        {
            const char* ph = (const char*)g_w1hi + srow * 512 + c * 128 + shalf * 64;
            const char* pl = (const char*)g_w1lo + srow * 512 + c * 128 + shalf * 64;
            char* dsth = sBhi + srow * 144 + shalf * 64;
            char* dstl = sBlo + srow * 144 + shalf * 64;
#pragma unroll
            for (int i = 0; i < 4; ++i) {
                *(uint4*)(dsth + i * 16) = *(const uint4*)(ph + i * 16);
                *(uint4*)(dstl + i * 16) = *(const uint4*)(pl + i * 16);
            }
        }
        __syncthreads();

        // ---- compute: 4 k16-steps per chunk
        const uint32_t lrow = lane & 15, lhalf = lane >> 4;
#pragma unroll
        for (int ks = 0; ks < 4; ++ks) {
            const uint32_t koff = (ks * 16 + lhalf * 8) * 2;   // bytes
            uint32_t ah[4], al[4];
            ldmx4(ah, uAhi + (w * 16 + lrow) * 144 + koff);
            ldmx4(al, uAlo + (w * 16 + lrow) * 144 + koff);
#pragma unroll
            for (int nt = 0; nt < 8; ++nt) {
                uint32_t bh[4], bl[4];
                ldmx4(bh, uBhi + (nt * 16 + lrow) * 144 + koff);
                ldmx4(bl, uBlo + (nt * 16 + lrow) * 144 + koff);
                mma16816(acc[2 * nt],     ah, bh[0], bh[2]);
                mma16816(acc[2 * nt + 1], ah, bh[1], bh[3]);
                mma16816(acc[2 * nt],     ah, bl[0], bl[2]);
                mma16816(acc[2 * nt + 1], ah, bl[1], bl[3]);
                mma16816(acc[2 * nt],     al, bh[0], bh[2]);
                mma16816(acc[2 * nt + 1], al, bh[1], bh[3]);
            }
        }
    }

    // ---- epilogue: bias + relu + layer2 dots, quad-reduce, store 2 rows/quad
    const int quad = lane >> 2;     // 0..7
    const int qt = lane & 3;        // 0..3
    float p0[4] = {0.f, 0.f, 0.f, 0.f};   // row1: y20,y21,o0,o1
    float p1[4] = {0.f, 0.f, 0.f, 0.f};   // row2
#pragma unroll
    for (int j = 0; j < 16; ++j) {
        int col0 = j * 8 + qt * 2;
        float h00 = fmaxf(acc[j][0] + s_b1[col0],     0.f);
        float h01 = fmaxf(acc[j][1] + s_b1[col0 + 1], 0.f);
        float h10 = fmaxf(acc[j][2] + s_b1[col0],     0.f);
        float h11 = fmaxf(acc[j][3] + s_b1[col0 + 1], 0.f);
#pragma unroll
        for (int o = 0; o < 4; ++o) {
            p0[o] += h00 * s_w2[o][col0] + h01 * s_w2[o][col0 + 1];
            p1[o] += h10 * s_w2[o][col0] + h11 * s_w2[o][col0 + 1];
        }
    }
#pragma unroll
    for (int m = 1; m <= 2; m <<= 1) {
#pragma unroll
        for (int o = 0; o < 4; ++o) {
            p0[o] += __shfl_xor_sync(0xFFFFFFFFu, p0[o], m);
            p1[o] += __shfl_xor_sync(0xFFFFFFFFu, p1[o], m);
        }
    }
    if (qt == 0) {
        float bb0 = b2[0], bb1 = b2[1];
        int r1 = m0 + w * 16 + quad;
        int r2 = r1 + 8;
        if (r1 < N_NODES) {
            *(float2*)(g_y2 + (size_t)r1 * 2) = make_float2(p0[0], p0[1]);
            *(float2*)(out + (size_t)r1 * 2) = make_float2(p0[2] + bb0, p0[3] + bb1);
        }
        if (r2 < N_NODES) {
            *(float2*)(g_y2 + (size_t)r2 * 2) = make_float2(p1[0], p1[1]);
            *(float2*)(out + (size_t)r2 * 2) = make_float2(p1[2] + bb0, p1[3] + bb1);
        }
    }
}

// ================= layer-2 aggregation of y2 (8 bytes/edge) ====================
__global__ void k_agg2(float* __restrict__ out) {
    int v = (blockIdx.x * blockDim.x + threadIdx.x) >> 5;
    int lane = threadIdx.x & 31;
    if (v >= N_NODES) return;
    int beg = g_off[v], end = g_off[v + 1];
    float a0 = 0.f, a1 = 0.f;
    for (int e = beg + lane; e < end; e += 32) {
        int s = g_ssrc[e];
        float2 y = ((const float2*)g_y2)[s];
        a0 += y.x; a1 += y.y;
    }
#pragma unroll
    for (int o = 16; o > 0; o >>= 1) {
        a0 += __shfl_xor_sync(0xFFFFFFFFu, a0, o);
        a1 += __shfl_xor_sync(0xFFFFFFFFu, a1, o);
    }
    if (lane == 0) {
        float inv = 1.0f / fmaxf((float)(end - beg), 1.0f);
        out[v * 2 + 0] += a0 * inv;
        out[v * 2 + 1] += a1 * inv;
    }
}

// ================= launch ======================================================
extern "C" void kernel_launch(void* const* d_in, const int* in_sizes, int n_in,
                              void* d_out, int out_size)
{
    const float* x    = (const float*)d_in[0];
    const int*   ei   = (const int*)d_in[1];
    const float* W1l  = (const float*)d_in[2];
    const float* W1r  = (const float*)d_in[3];
    const float* b1   = (const float*)d_in[4];
    const float* W2l  = (const float*)d_in[5];
    const float* W2r  = (const float*)d_in[6];
    const float* b2   = (const float*)d_in[7];
    float* out = (float*)d_out;

    const int DSMEM = 4 * TBYTES;   // 73728 B
    cudaFuncSetAttribute(k_gemm_mma, cudaFuncAttributeMaxDynamicSharedMemorySize, DSMEM);

    k_zero_deg<<<(N_NODES + 255) / 256, 256>>>();
    k_hist<<<N_EDGES / 256, 256>>>(ei);
    k_scan<<<1, 1024>>>();
    k_bin<<<N_EDGES / 256, 256>>>(ei);
    k_agg1<<<(N_NODES * 32 + 255) / 256, 256>>>(x);
    k_prep_w<<<128, 256>>>(W1l, W1r);
    k_gemm_mma<<<(N_NODES + 127) / 128, 256, DSMEM>>>(x, b1, W2l, W2r, b2, out);
    k_agg2<<<(N_NODES * 32 + 255) / 256, 256>>>(out);
}

// round 9
// speedup vs baseline: 1.4130x; 1.0752x over previous
#include <cuda_runtime.h>
#include <cuda_bf16.h>
#include <cstdint>

#define N_NODES 50000
#define N_EDGES 800000
#define D 128

// ================= scratch =====================================================
__device__ __align__(16) int   g_deg[N_NODES];
__device__ __align__(16) int   g_off[N_NODES + 1];
__device__ __align__(16) int   g_cur[N_NODES];
__device__ __align__(16) int   g_ssrc[N_EDGES];
__device__ __align__(16) float g_agg[(size_t)N_NODES * D];   // mean-agg of x
__device__ __align__(16) float g_y2[(size_t)N_NODES * 2];    // h @ W2_l^T
__device__ __align__(16) __nv_bfloat16 g_w1hi[128 * 256];    // [Wl|Wr] hi split
__device__ __align__(16) __nv_bfloat16 g_w1lo[128 * 256];    // [Wl|Wr] lo split

// ================= helpers =====================================================
__device__ __forceinline__ uint32_t smem_u32(const void* p) {
    uint32_t a;
    asm("{ .reg .u64 t; cvta.to.shared.u64 t, %1; cvt.u32.u64 %0, t; }"
        : "=r"(a) : "l"(p));
    return a;
}

__device__ __forceinline__ void ldmx4(uint32_t* r, uint32_t addr) {
    asm volatile("ldmatrix.sync.aligned.m8n8.x4.shared.b16 {%0,%1,%2,%3}, [%4];"
        : "=r"(r[0]), "=r"(r[1]), "=r"(r[2]), "=r"(r[3]) : "r"(addr));
}

__device__ __forceinline__ void mma16816(float* d, const uint32_t* a,
                                         uint32_t b0, uint32_t b1) {
    asm volatile("mma.sync.aligned.m16n8k16.row.col.f32.bf16.bf16.f32 "
        "{%0,%1,%2,%3}, {%4,%5,%6,%7}, {%8,%9}, {%0,%1,%2,%3};"
        : "+f"(d[0]), "+f"(d[1]), "+f"(d[2]), "+f"(d[3])
        : "r"(a[0]), "r"(a[1]), "r"(a[2]), "r"(a[3]), "r"(b0), "r"(b1));
}

// split 8 fp32 -> packed bf16 hi (uint4) and lo residual (uint4)
__device__ __forceinline__ void split8(float4 u, float4 w, uint4& hv, uint4& lv) {
    float f[8] = {u.x, u.y, u.z, u.w, w.x, w.y, w.z, w.w};
    uint32_t hi[8], lo[8];
#pragma unroll
    for (int t = 0; t < 8; ++t) {
        __nv_bfloat16 h = __float2bfloat16(f[t]);
        hi[t] = (uint32_t)__bfloat16_as_ushort(h);
        lo[t] = (uint32_t)__bfloat16_as_ushort(__float2bfloat16(f[t] - __bfloat162float(h)));
    }
    hv = make_uint4(hi[0] | (hi[1] << 16), hi[2] | (hi[3] << 16),
                    hi[4] | (hi[5] << 16), hi[6] | (hi[7] << 16));
    lv = make_uint4(lo[0] | (lo[1] << 16), lo[2] | (lo[3] << 16),
                    lo[4] | (lo[5] << 16), lo[6] | (lo[7] << 16));
}

// ================= prep: zero deg + split weights (merged, independent) ========
__global__ void k_zero_prep(const float* __restrict__ Wl, const float* __restrict__ Wr) {
    int b = blockIdx.x;
    if (b < 196) {                      // zero g_deg
        int i = b * 256 + threadIdx.x;
        if (i < N_NODES) g_deg[i] = 0;
    } else {                            // weight bf16 hi/lo split: 128 rows
        int j = b - 196;                // 0..127
        int k = threadIdx.x;            // 0..255
        float v = (k < 128) ? Wl[j * 128 + k] : Wr[j * 128 + (k - 128)];
        __nv_bfloat16 h = __float2bfloat16(v);
        g_w1hi[j * 256 + k] = h;
        g_w1lo[j * 256 + k] = __float2bfloat16(v - __bfloat162float(h));
    }
}

// ================= hist / bin: 8 edges per thread (MLP) ========================
#define EPT 8
#define PREP_BLOCKS ((N_EDGES + 256 * EPT - 1) / (256 * EPT))   // 391

__global__ void k_hist(const int* __restrict__ ei) {
    int t0 = (blockIdx.x * blockDim.x + threadIdx.x) * EPT;
    int dsts[EPT];
#pragma unroll
    for (int i = 0; i < EPT; ++i) {
        int e = t0 + i;
        dsts[i] = (e < N_EDGES) ? ei[N_EDGES + e] : -1;
    }
#pragma unroll
    for (int i = 0; i < EPT; ++i)
        if ((unsigned)dsts[i] < (unsigned)N_NODES) atomicAdd(&g_deg[dsts[i]], 1);
}

__global__ void k_scan() {
    __shared__ int sums[1024];
    int t = threadIdx.x;
    const int CH = (N_NODES + 1023) / 1024;
    int begin = t * CH;
    int end = begin + CH; if (end > N_NODES) end = N_NODES;
    int s = 0;
    for (int i = begin; i < end; ++i) s += g_deg[i];
    sums[t] = s;
    __syncthreads();
    for (int off = 1; off < 1024; off <<= 1) {
        int v = (t >= off) ? sums[t - off] : 0;
        __syncthreads();
        if (t >= off) sums[t] += v;
        __syncthreads();
    }
    int base = (t == 0) ? 0 : sums[t - 1];
    for (int i = begin; i < end; ++i) {
        g_off[i] = base;
        g_cur[i] = base;
        base += g_deg[i];
    }
    if (t == 1023) g_off[N_NODES] = sums[1023];
}

__global__ void k_bin(const int* __restrict__ ei) {
    int t0 = (blockIdx.x * blockDim.x + threadIdx.x) * EPT;
    int srcs[EPT], dsts[EPT];
#pragma unroll
    for (int i = 0; i < EPT; ++i) {
        int e = t0 + i;
        srcs[i] = (e < N_EDGES) ? ei[e] : -1;
        dsts[i] = (e < N_EDGES) ? ei[N_EDGES + e] : -1;
    }
#pragma unroll
    for (int i = 0; i < EPT; ++i) {
        if ((unsigned)dsts[i] < (unsigned)N_NODES && (unsigned)srcs[i] < (unsigned)N_NODES) {
            int p = atomicAdd(&g_cur[dsts[i]], 1);
            if ((unsigned)p < (unsigned)N_EDGES) g_ssrc[p] = srcs[i];
        }
    }
}

// ================= layer-1 aggregation: warp/node, unroll x4 ===================
__global__ void k_agg1(const float* __restrict__ x) {
    int w = (blockIdx.x * blockDim.x + threadIdx.x) >> 5;
    int lane = threadIdx.x & 31;
    if (w >= N_NODES) return;
    int beg = g_off[w], end = g_off[w + 1];
    float4 acc = make_float4(0.f, 0.f, 0.f, 0.f);
    const float4* xv = (const float4*)x;
    int e = beg;
    for (; e + 4 <= end; e += 4) {
        int s0 = g_ssrc[e], s1 = g_ssrc[e + 1], s2 = g_ssrc[e + 2], s3 = g_ssrc[e + 3];
        float4 v0 = xv[(size_t)s0 * 32 + lane];
        float4 v1 = xv[(size_t)s1 * 32 + lane];
        float4 v2 = xv[(size_t)s2 * 32 + lane];
        float4 v3 = xv[(size_t)s3 * 32 + lane];
        acc.x += (v0.x + v1.x) + (v2.x + v3.x);
        acc.y += (v0.y + v1.y) + (v2.y + v3.y);
        acc.z += (v0.z + v1.z) + (v2.z + v3.z);
        acc.w += (v0.w + v1.w) + (v2.w + v3.w);
    }
    for (; e < end; ++e) {
        int s = g_ssrc[e];
        float4 v = xv[(size_t)s * 32 + lane];
        acc.x += v.x; acc.y += v.y; acc.z += v.z; acc.w += v.w;
    }
    float inv = 1.0f / fmaxf((float)(end - beg), 1.0f);
    float4* o = (float4*)g_agg;
    o[(size_t)w * 32 + lane] = make_float4(acc.x * inv, acc.y * inv, acc.z * inv, acc.w * inv);
}

// ================= fused layer1 GEMM (warp mma) + layer2 self ==================
#define TSTRIDE 72            // bf16 elements per row (144 bytes)
#define TBYTES  (128 * TSTRIDE * 2)   // 18432 per tile

__global__ void __launch_bounds__(256, 2) k_gemm_mma(
    const float* __restrict__ x,
    const float* __restrict__ b1g,
    const float* __restrict__ W2l, const float* __restrict__ W2r,
    const float* __restrict__ b2,
    float* __restrict__ out)
{
    extern __shared__ char dynsm[];
    char* sAhi = dynsm;
    char* sAlo = dynsm + TBYTES;
    char* sBhi = dynsm + 2 * TBYTES;
    char* sBlo = dynsm + 3 * TBYTES;
    __shared__ float s_b1[128];
    __shared__ float s_w2[4][128];

    const int tid = threadIdx.x;
    const int w = tid >> 5;
    const int lane = tid & 31;
    const int m0 = blockIdx.x * 128;

    if (tid < 128) {
        s_b1[tid] = b1g[tid];
        s_w2[0][tid] = W2l[tid];
        s_w2[1][tid] = W2l[128 + tid];
        s_w2[2][tid] = W2r[tid];
        s_w2[3][tid] = W2r[128 + tid];
    }

    const uint32_t uAhi = smem_u32(sAhi), uAlo = smem_u32(sAlo);
    const uint32_t uBhi = smem_u32(sBhi), uBlo = smem_u32(sBlo);

    float acc[16][4];
#pragma unroll
    for (int j = 0; j < 16; ++j)
#pragma unroll
        for (int q = 0; q < 4; ++q) acc[j][q] = 0.f;

    const int srow = tid >> 1;          // staging row 0..127
    const int shalf = tid & 1;          // 0/1 -> 32-element half

    for (int c = 0; c < 4; ++c) {
        if (c) __syncthreads();         // previous chunk's mma reads done
        // ---- stage A: fp32 -> bf16 hi/lo, 32 elems per thread
        {
            int node = m0 + srow;
            bool valid = node < N_NODES;
            const float* basep = (c < 2) ? g_agg : x;
            const float* srcp = basep + (size_t)(valid ? node : 0) * D
                                + (c & 1) * 64 + shalf * 32;
            char* dsth = sAhi + srow * 144 + shalf * 64;
            char* dstl = sAlo + srow * 144 + shalf * 64;
#pragma unroll
            for (int i = 0; i < 4; ++i) {
                float4 u = make_float4(0.f, 0.f, 0.f, 0.f);
                float4 v = make_float4(0.f, 0.f, 0.f, 0.f);
                if (valid) {
                    u = *(const float4*)(srcp + i * 8);
                    v = *(const float4*)(srcp + i * 8 + 4);
                }
                uint4 hv, lv;
                split8(u, v, hv, lv);
                *(uint4*)(dsth + i * 16) = hv;
                *(uint4*)(dstl + i * 16) = lv;
            }
        }
        // ---- stage B: copy pre-split bf16 weights
        {
            const char* ph = (const char*)g_w1hi + srow * 512 + c * 128 + shalf * 64;
            const char* pl = (const char*)g_w1lo + srow * 512 + c * 128 + shalf * 64;
            char* dsth = sBhi + srow * 144 + shalf * 64;
            char* dstl = sBlo + srow * 144 + shalf * 64;
#pragma unroll
            for (int i = 0; i < 4; ++i) {
                *(uint4*)(dsth + i * 16) = *(const uint4*)(ph + i * 16);
                *(uint4*)(dstl + i * 16) = *(const uint4*)(pl + i * 16);
            }
        }
        __syncthreads();

        // ---- compute: 4 k16-steps per chunk
        const uint32_t lrow = lane & 15, lhalf = lane >> 4;
#pragma unroll
        for (int ks = 0; ks < 4; ++ks) {
            const uint32_t koff = (ks * 16 + lhalf * 8) * 2;   // bytes
            uint32_t ah[4], al[4];
            ldmx4(ah, uAhi + (w * 16 + lrow) * 144 + koff);
            ldmx4(al, uAlo + (w * 16 + lrow) * 144 + koff);
#pragma unroll
            for (int nt = 0; nt < 8; ++nt) {
                uint32_t bh[4], bl[4];
                ldmx4(bh, uBhi + (nt * 16 + lrow) * 144 + koff);
                ldmx4(bl, uBlo + (nt * 16 + lrow) * 144 + koff);
                mma16816(acc[2 * nt],     ah, bh[0], bh[2]);
                mma16816(acc[2 * nt + 1], ah, bh[1], bh[3]);
                mma16816(acc[2 * nt],     ah, bl[0], bl[2]);
                mma16816(acc[2 * nt + 1], ah, bl[1], bl[3]);
                mma16816(acc[2 * nt],     al, bh[0], bh[2]);
                mma16816(acc[2 * nt + 1], al, bh[1], bh[3]);
            }
        }
    }

    // ---- epilogue: bias + relu + layer2 dots, quad-reduce, store 2 rows/quad
    const int quad = lane >> 2;     // 0..7
    const int qt = lane & 3;        // 0..3
    float p0[4] = {0.f, 0.f, 0.f, 0.f};   // row1: y20,y21,o0,o1
    float p1[4] = {0.f, 0.f, 0.f, 0.f};   // row2
#pragma unroll
    for (int j = 0; j < 16; ++j) {
        int col0 = j * 8 + qt * 2;
        float h00 = fmaxf(acc[j][0] + s_b1[col0],     0.f);
        float h01 = fmaxf(acc[j][1] + s_b1[col0 + 1], 0.f);
        float h10 = fmaxf(acc[j][2] + s_b1[col0],     0.f);
        float h11 = fmaxf(acc[j][3] + s_b1[col0 + 1], 0.f);
#pragma unroll
        for (int o = 0; o < 4; ++o) {
            p0[o] += h00 * s_w2[o][col0] + h01 * s_w2[o][col0 + 1];
            p1[o] += h10 * s_w2[o][col0] + h11 * s_w2[o][col0 + 1];
        }
    }
#pragma unroll
    for (int m = 1; m <= 2; m <<= 1) {
#pragma unroll
        for (int o = 0; o < 4; ++o) {
            p0[o] += __shfl_xor_sync(0xFFFFFFFFu, p0[o], m);
            p1[o] += __shfl_xor_sync(0xFFFFFFFFu, p1[o], m);
        }
    }
    if (qt == 0) {
        float bb0 = b2[0], bb1 = b2[1];
        int r1 = m0 + w * 16 + quad;
        int r2 = r1 + 8;
        if (r1 < N_NODES) {
            *(float2*)(g_y2 + (size_t)r1 * 2) = make_float2(p0[0], p0[1]);
            *(float2*)(out + (size_t)r1 * 2) = make_float2(p0[2] + bb0, p0[3] + bb1);
        }
        if (r2 < N_NODES) {
            *(float2*)(g_y2 + (size_t)r2 * 2) = make_float2(p1[0], p1[1]);
            *(float2*)(out + (size_t)r2 * 2) = make_float2(p1[2] + bb0, p1[3] + bb1);
        }
    }
}

// ================= layer-2 aggregation of y2 (8 bytes/edge) ====================
__global__ void k_agg2(float* __restrict__ out) {
    int v = (blockIdx.x * blockDim.x + threadIdx.x) >> 5;
    int lane = threadIdx.x & 31;
    if (v >= N_NODES) return;
    int beg = g_off[v], end = g_off[v + 1];
    float a0 = 0.f, a1 = 0.f;
    for (int e = beg + lane; e < end; e += 32) {
        int s = g_ssrc[e];
        float2 y = ((const float2*)g_y2)[s];
        a0 += y.x; a1 += y.y;
    }
#pragma unroll
    for (int o = 16; o > 0; o >>= 1) {
        a0 += __shfl_xor_sync(0xFFFFFFFFu, a0, o);
        a1 += __shfl_xor_sync(0xFFFFFFFFu, a1, o);
    }
    if (lane == 0) {
        float inv = 1.0f / fmaxf((float)(end - beg), 1.0f);
        out[v * 2 + 0] += a0 * inv;
        out[v * 2 + 1] += a1 * inv;
    }
}

// ================= launch ======================================================
extern "C" void kernel_launch(void* const* d_in, const int* in_sizes, int n_in,
                              void* d_out, int out_size)
{
    const float* x    = (const float*)d_in[0];
    const int*   ei   = (const int*)d_in[1];
    const float* W1l  = (const float*)d_in[2];
    const float* W1r  = (const float*)d_in[3];
    const float* b1   = (const float*)d_in[4];
    const float* W2l  = (const float*)d_in[5];
    const float* W2r  = (const float*)d_in[6];
    const float* b2   = (const float*)d_in[7];
    float* out = (float*)d_out;

    const int DSMEM = 4 * TBYTES;   // 73728 B
    cudaFuncSetAttribute(k_gemm_mma, cudaFuncAttributeMaxDynamicSharedMemorySize, DSMEM);

    k_zero_prep<<<196 + 128, 256>>>(W1l, W1r);
    k_hist<<<PREP_BLOCKS, 256>>>(ei);
    k_scan<<<1, 1024>>>();
    k_bin<<<PREP_BLOCKS, 256>>>(ei);
    k_agg1<<<(N_NODES * 32 + 255) / 256, 256>>>(x);
    k_gemm_mma<<<(N_NODES + 127) / 128, 256, DSMEM>>>(x, b1, W2l, W2r, b2, out);
    k_agg2<<<(N_NODES * 32 + 255) / 256, 256>>>(out);
}

// round 10
// speedup vs baseline: 2.3457x; 1.6600x over previous
#include <cuda_runtime.h>
#include <cuda_bf16.h>
#include <cstdint>

#define N_NODES 50000
#define N_EDGES 800000
#define D 128
#define CAP 128            // bucket capacity per dst (Poisson(16): overflow ~1e-60)

// ================= scratch =====================================================
__device__ __align__(16) int   g_deg[N_NODES];
__device__ __align__(16) int   g_bkt[(size_t)N_NODES * CAP];  // src buckets
__device__ __align__(16) float g_agg[(size_t)N_NODES * D];    // mean-agg of x
__device__ __align__(16) float g_y2[(size_t)N_NODES * 2];     // h @ W2_l^T
__device__ __align__(16) __nv_bfloat16 g_w1hi[128 * 256];     // [Wl|Wr] hi split
__device__ __align__(16) __nv_bfloat16 g_w1lo[128 * 256];     // [Wl|Wr] lo split

// ================= helpers =====================================================
__device__ __forceinline__ uint32_t smem_u32(const void* p) {
    uint32_t a;
    asm("{ .reg .u64 t; cvta.to.shared.u64 t, %1; cvt.u32.u64 %0, t; }"
        : "=r"(a) : "l"(p));
    return a;
}

__device__ __forceinline__ void ldmx4(uint32_t* r, uint32_t addr) {
    asm volatile("ldmatrix.sync.aligned.m8n8.x4.shared.b16 {%0,%1,%2,%3}, [%4];"
        : "=r"(r[0]), "=r"(r[1]), "=r"(r[2]), "=r"(r[3]) : "r"(addr));
}

__device__ __forceinline__ void mma16816(float* d, const uint32_t* a,
                                         uint32_t b0, uint32_t b1) {
    asm volatile("mma.sync.aligned.m16n8k16.row.col.f32.bf16.bf16.f32 "
        "{%0,%1,%2,%3}, {%4,%5,%6,%7}, {%8,%9}, {%0,%1,%2,%3};"
        : "+f"(d[0]), "+f"(d[1]), "+f"(d[2]), "+f"(d[3])
        : "r"(a[0]), "r"(a[1]), "r"(a[2]), "r"(a[3]), "r"(b0), "r"(b1));
}

// split 8 fp32 -> packed bf16 hi (uint4) and lo residual (uint4)
__device__ __forceinline__ void split8(float4 u, float4 w, uint4& hv, uint4& lv) {
    float f[8] = {u.x, u.y, u.z, u.w, w.x, w.y, w.z, w.w};
    uint32_t hi[8], lo[8];
#pragma unroll
    for (int t = 0; t < 8; ++t) {
        __nv_bfloat16 h = __float2bfloat16(f[t]);
        hi[t] = (uint32_t)__bfloat16_as_ushort(h);
        lo[t] = (uint32_t)__bfloat16_as_ushort(__float2bfloat16(f[t] - __bfloat162float(h)));
    }
    hv = make_uint4(hi[0] | (hi[1] << 16), hi[2] | (hi[3] << 16),
                    hi[4] | (hi[5] << 16), hi[6] | (hi[7] << 16));
    lv = make_uint4(lo[0] | (lo[1] << 16), lo[2] | (lo[3] << 16),
                    lo[4] | (lo[5] << 16), lo[6] | (lo[7] << 16));
}

// ================= prep: zero deg + split weights (merged, independent) ========
__global__ void k_zero_prep(const float* __restrict__ Wl, const float* __restrict__ Wr) {
    int b = blockIdx.x;
    if (b < 196) {                      // zero g_deg
        int i = b * 256 + threadIdx.x;
        if (i < N_NODES) g_deg[i] = 0;
    } else {                            // weight bf16 hi/lo split: 128 rows
        int j = b - 196;                // 0..127
        int k = threadIdx.x;            // 0..255
        float v = (k < 128) ? Wl[j * 128 + k] : Wr[j * 128 + (k - 128)];
        __nv_bfloat16 h = __float2bfloat16(v);
        g_w1hi[j * 256 + k] = h;
        g_w1lo[j * 256 + k] = __float2bfloat16(v - __bfloat162float(h));
    }
}

// ================= single-pass binning: 8 edges per thread =====================
#define EPT 8
#define PREP_BLOCKS ((N_EDGES + 256 * EPT - 1) / (256 * EPT))   // 391

__global__ void k_bin(const int* __restrict__ ei) {
    int t0 = (blockIdx.x * blockDim.x + threadIdx.x) * EPT;
    int srcs[EPT], dsts[EPT];
#pragma unroll
    for (int i = 0; i < EPT; ++i) {
        int e = t0 + i;
        srcs[i] = (e < N_EDGES) ? ei[e] : -1;
        dsts[i] = (e < N_EDGES) ? ei[N_EDGES + e] : -1;
    }
#pragma unroll
    for (int i = 0; i < EPT; ++i) {
        if ((unsigned)dsts[i] < (unsigned)N_NODES && (unsigned)srcs[i] < (unsigned)N_NODES) {
            int slot = atomicAdd(&g_deg[dsts[i]], 1);
            if (slot < CAP) g_bkt[(size_t)dsts[i] * CAP + slot] = srcs[i];
        }
    }
}

// ================= layer-1 aggregation: warp/node, unroll x4 ===================
__global__ void k_agg1(const float* __restrict__ x) {
    int w = (blockIdx.x * blockDim.x + threadIdx.x) >> 5;
    int lane = threadIdx.x & 31;
    if (w >= N_NODES) return;
    int deg = g_deg[w]; if (deg > CAP) deg = CAP;
    const int* bkt = g_bkt + (size_t)w * CAP;
    float4 acc = make_float4(0.f, 0.f, 0.f, 0.f);
    const float4* xv = (const float4*)x;
    int e = 0;
    for (; e + 4 <= deg; e += 4) {
        int s0 = bkt[e], s1 = bkt[e + 1], s2 = bkt[e + 2], s3 = bkt[e + 3];
        float4 v0 = xv[(size_t)s0 * 32 + lane];
        float4 v1 = xv[(size_t)s1 * 32 + lane];
        float4 v2 = xv[(size_t)s2 * 32 + lane];
        float4 v3 = xv[(size_t)s3 * 32 + lane];
        acc.x += (v0.x + v1.x) + (v2.x + v3.x);
        acc.y += (v0.y + v1.y) + (v2.y + v3.y);
        acc.z += (v0.z + v1.z) + (v2.z + v3.z);
        acc.w += (v0.w + v1.w) + (v2.w + v3.w);
    }
    for (; e < deg; ++e) {
        int s = bkt[e];
        float4 v = xv[(size_t)s * 32 + lane];
        acc.x += v.x; acc.y += v.y; acc.z += v.z; acc.w += v.w;
    }
    float inv = 1.0f / fmaxf((float)deg, 1.0f);
    float4* o = (float4*)g_agg;
    o[(size_t)w * 32 + lane] = make_float4(acc.x * inv, acc.y * inv, acc.z * inv, acc.w * inv);
}

// ================= fused layer1 GEMM (warp mma) + layer2 self ==================
#define TSTRIDE 72            // bf16 elements per row (144 bytes)
#define TBYTES  (128 * TSTRIDE * 2)   // 18432 per tile

__global__ void __launch_bounds__(256, 2) k_gemm_mma(
    const float* __restrict__ x,
    const float* __restrict__ b1g,
    const float* __restrict__ W2l, const float* __restrict__ W2r,
    const float* __restrict__ b2,
    float* __restrict__ out)
{
    extern __shared__ char dynsm[];
    char* sAhi = dynsm;
    char* sAlo = dynsm + TBYTES;
    char* sBhi = dynsm + 2 * TBYTES;
    char* sBlo = dynsm + 3 * TBYTES;
    __shared__ float s_b1[128];
    __shared__ float s_w2[4][128];

    const int tid = threadIdx.x;
    const int w = tid >> 5;
    const int lane = tid & 31;
    const int m0 = blockIdx.x * 128;

    if (tid < 128) {
        s_b1[tid] = b1g[tid];
        s_w2[0][tid] = W2l[tid];
        s_w2[1][tid] = W2l[128 + tid];
        s_w2[2][tid] = W2r[tid];
        s_w2[3][tid] = W2r[128 + tid];
    }

    const uint32_t uAhi = smem_u32(sAhi), uAlo = smem_u32(sAlo);
    const uint32_t uBhi = smem_u32(sBhi), uBlo = smem_u32(sBlo);

    float acc[16][4];
#pragma unroll
    for (int j = 0; j < 16; ++j)
#pragma unroll
        for (int q = 0; q < 4; ++q) acc[j][q] = 0.f;

    const int srow = tid >> 1;          // staging row 0..127
    const int shalf = tid & 1;          // 0/1 -> 32-element half

    for (int c = 0; c < 4; ++c) {
        if (c) __syncthreads();         // previous chunk's mma reads done
        // ---- stage A: fp32 -> bf16 hi/lo, 32 elems per thread
        {
            int node = m0 + srow;
            bool valid = node < N_NODES;
            const float* basep = (c < 2) ? g_agg : x;
            const float* srcp = basep + (size_t)(valid ? node : 0) * D
                                + (c & 1) * 64 + shalf * 32;
            char* dsth = sAhi + srow * 144 + shalf * 64;
            char* dstl = sAlo + srow * 144 + shalf * 64;
#pragma unroll
            for (int i = 0; i < 4; ++i) {
                float4 u = make_float4(0.f, 0.f, 0.f, 0.f);
                float4 v = make_float4(0.f, 0.f, 0.f, 0.f);
                if (valid) {
                    u = *(const float4*)(srcp + i * 8);
                    v = *(const float4*)(srcp + i * 8 + 4);
                }
                uint4 hv, lv;
                split8(u, v, hv, lv);
                *(uint4*)(dsth + i * 16) = hv;
                *(uint4*)(dstl + i * 16) = lv;
            }
        }
        // ---- stage B: copy pre-split bf16 weights
        {
            const char* ph = (const char*)g_w1hi + srow * 512 + c * 128 + shalf * 64;
            const char* pl = (const char*)g_w1lo + srow * 512 + c * 128 + shalf * 64;
            char* dsth = sBhi + srow * 144 + shalf * 64;
            char* dstl = sBlo + srow * 144 + shalf * 64;
#pragma unroll
            for (int i = 0; i < 4; ++i) {
                *(uint4*)(dsth + i * 16) = *(const uint4*)(ph + i * 16);
                *(uint4*)(dstl + i * 16) = *(const uint4*)(pl + i * 16);
            }
        }
        __syncthreads();

        // ---- compute: 4 k16-steps per chunk
        const uint32_t lrow = lane & 15, lhalf = lane >> 4;
#pragma unroll
        for (int ks = 0; ks < 4; ++ks) {
            const uint32_t koff = (ks * 16 + lhalf * 8) * 2;   // bytes
            uint32_t ah[4], al[4];
            ldmx4(ah, uAhi + (w * 16 + lrow) * 144 + koff);
            ldmx4(al, uAlo + (w * 16 + lrow) * 144 + koff);
#pragma unroll
            for (int nt = 0; nt < 8; ++nt) {
                uint32_t bh[4], bl[4];
                ldmx4(bh, uBhi + (nt * 16 + lrow) * 144 + koff);
                ldmx4(bl, uBlo + (nt * 16 + lrow) * 144 + koff);
                mma16816(acc[2 * nt],     ah, bh[0], bh[2]);
                mma16816(acc[2 * nt + 1], ah, bh[1], bh[3]);
                mma16816(acc[2 * nt],     ah, bl[0], bl[2]);
                mma16816(acc[2 * nt + 1], ah, bl[1], bl[3]);
                mma16816(acc[2 * nt],     al, bh[0], bh[2]);
                mma16816(acc[2 * nt + 1], al, bh[1], bh[3]);
            }
        }
    }

    // ---- epilogue: bias + relu + layer2 dots, quad-reduce, store 2 rows/quad
    const int quad = lane >> 2;     // 0..7
    const int qt = lane & 3;        // 0..3
    float p0[4] = {0.f, 0.f, 0.f, 0.f};   // row1: y20,y21,o0,o1
    float p1[4] = {0.f, 0.f, 0.f, 0.f};   // row2
#pragma unroll
    for (int j = 0; j < 16; ++j) {
        int col0 = j * 8 + qt * 2;
        float h00 = fmaxf(acc[j][0] + s_b1[col0],     0.f);
        float h01 = fmaxf(acc[j][1] + s_b1[col0 + 1], 0.f);
        float h10 = fmaxf(acc[j][2] + s_b1[col0],     0.f);
        float h11 = fmaxf(acc[j][3] + s_b1[col0 + 1], 0.f);
#pragma unroll
        for (int o = 0; o < 4; ++o) {
            p0[o] += h00 * s_w2[o][col0] + h01 * s_w2[o][col0 + 1];
            p1[o] += h10 * s_w2[o][col0] + h11 * s_w2[o][col0 + 1];
        }
    }
#pragma unroll
    for (int m = 1; m <= 2; m <<= 1) {
#pragma unroll
        for (int o = 0; o < 4; ++o) {
            p0[o] += __shfl_xor_sync(0xFFFFFFFFu, p0[o], m);
            p1[o] += __shfl_xor_sync(0xFFFFFFFFu, p1[o], m);
        }
    }
    if (qt == 0) {
        float bb0 = b2[0], bb1 = b2[1];
        int r1 = m0 + w * 16 + quad;
        int r2 = r1 + 8;
        if (r1 < N_NODES) {
            *(float2*)(g_y2 + (size_t)r1 * 2) = make_float2(p0[0], p0[1]);
            *(float2*)(out + (size_t)r1 * 2) = make_float2(p0[2] + bb0, p0[3] + bb1);
        }
        if (r2 < N_NODES) {
            *(float2*)(g_y2 + (size_t)r2 * 2) = make_float2(p1[0], p1[1]);
            *(float2*)(out + (size_t)r2 * 2) = make_float2(p1[2] + bb0, p1[3] + bb1);
        }
    }
}

// ================= layer-2 aggregation of y2 (8 bytes/edge) ====================
__global__ void k_agg2(float* __restrict__ out) {
    int v = (blockIdx.x * blockDim.x + threadIdx.x) >> 5;
    int lane = threadIdx.x & 31;
    if (v >= N_NODES) return;
    int deg = g_deg[v]; if (deg > CAP) deg = CAP;
    const int* bkt = g_bkt + (size_t)v * CAP;
    float a0 = 0.f, a1 = 0.f;
    for (int e = lane; e < deg; e += 32) {
        int s = bkt[e];
        float2 y = ((const float2*)g_y2)[s];
        a0 += y.x; a1 += y.y;
    }
#pragma unroll
    for (int o = 16; o > 0; o >>= 1) {
        a0 += __shfl_xor_sync(0xFFFFFFFFu, a0, o);
        a1 += __shfl_xor_sync(0xFFFFFFFFu, a1, o);
    }
    if (lane == 0) {
        float inv = 1.0f / fmaxf((float)deg, 1.0f);
        out[v * 2 + 0] += a0 * inv;
        out[v * 2 + 1] += a1 * inv;
    }
}

// ================= launch ======================================================
extern "C" void kernel_launch(void* const* d_in, const int* in_sizes, int n_in,
                              void* d_out, int out_size)
{
    const float* x    = (const float*)d_in[0];
    const int*   ei   = (const int*)d_in[1];
    const float* W1l  = (const float*)d_in[2];
    const float* W1r  = (const float*)d_in[3];
    const float* b1   = (const float*)d_in[4];
    const float* W2l  = (const float*)d_in[5];
    const float* W2r  = (const float*)d_in[6];
    const float* b2   = (const float*)d_in[7];
    float* out = (float*)d_out;

    const int DSMEM = 4 * TBYTES;   // 73728 B
    cudaFuncSetAttribute(k_gemm_mma, cudaFuncAttributeMaxDynamicSharedMemorySize, DSMEM);

    k_zero_prep<<<196 + 128, 256>>>(W1l, W1r);
    k_bin<<<PREP_BLOCKS, 256>>>(ei);
    k_agg1<<<(N_NODES * 32 + 255) / 256, 256>>>(x);
    k_gemm_mma<<<(N_NODES + 127) / 128, 256, DSMEM>>>(x, b1, W2l, W2r, b2, out);
    k_agg2<<<(N_NODES * 32 + 255) / 256, 256>>>(out);
}

// round 11
// speedup vs baseline: 2.4299x; 1.0359x over previous
#include <cuda_runtime.h>
#include <cuda_bf16.h>
#include <cstdint>

#define N_NODES 50000
#define N_EDGES 800000
#define D 128
#define CAP 128            // bucket capacity per dst (Poisson(16): overflow ~1e-60)

// ================= scratch =====================================================
__device__ __align__(16) int   g_deg[N_NODES];
__device__ __align__(16) int   g_bkt[(size_t)N_NODES * CAP];  // src buckets
__device__ __align__(16) float g_agg[(size_t)N_NODES * D];    // mean-agg of x
__device__ __align__(16) float g_y2[(size_t)N_NODES * 2];     // h @ W2_l^T
__device__ __align__(16) __nv_bfloat16 g_w1hi[128 * 256];     // [Wl|Wr] hi split
__device__ __align__(16) __nv_bfloat16 g_w1lo[128 * 256];     // [Wl|Wr] lo split

// ================= helpers =====================================================
__device__ __forceinline__ uint32_t smem_u32(const void* p) {
    uint32_t a;
    asm("{ .reg .u64 t; cvta.to.shared.u64 t, %1; cvt.u32.u64 %0, t; }"
        : "=r"(a) : "l"(p));
    return a;
}

__device__ __forceinline__ void ldmx4(uint32_t* r, uint32_t addr) {
    asm volatile("ldmatrix.sync.aligned.m8n8.x4.shared.b16 {%0,%1,%2,%3}, [%4];"
        : "=r"(r[0]), "=r"(r[1]), "=r"(r[2]), "=r"(r[3]) : "r"(addr));
}

__device__ __forceinline__ void mma16816(float* d, const uint32_t* a,
                                         uint32_t b0, uint32_t b1) {
    asm volatile("mma.sync.aligned.m16n8k16.row.col.f32.bf16.bf16.f32 "
        "{%0,%1,%2,%3}, {%4,%5,%6,%7}, {%8,%9}, {%0,%1,%2,%3};"
        : "+f"(d[0]), "+f"(d[1]), "+f"(d[2]), "+f"(d[3])
        : "r"(a[0]), "r"(a[1]), "r"(a[2]), "r"(a[3]), "r"(b0), "r"(b1));
}

// split 8 fp32 -> packed bf16 hi (uint4) and lo residual (uint4)
__device__ __forceinline__ void split8(float4 u, float4 w, uint4& hv, uint4& lv) {
    float f[8] = {u.x, u.y, u.z, u.w, w.x, w.y, w.z, w.w};
    uint32_t hi[8], lo[8];
#pragma unroll
    for (int t = 0; t < 8; ++t) {
        __nv_bfloat16 h = __float2bfloat16(f[t]);
        hi[t] = (uint32_t)__bfloat16_as_ushort(h);
        lo[t] = (uint32_t)__bfloat16_as_ushort(__float2bfloat16(f[t] - __bfloat162float(h)));
    }
    hv = make_uint4(hi[0] | (hi[1] << 16), hi[2] | (hi[3] << 16),
                    hi[4] | (hi[5] << 16), hi[6] | (hi[7] << 16));
    lv = make_uint4(lo[0] | (lo[1] << 16), lo[2] | (lo[3] << 16),
                    lo[4] | (lo[5] << 16), lo[6] | (lo[7] << 16));
}

// ================= prep: zero deg + split weights (merged, independent) ========
__global__ void k_zero_prep(const float* __restrict__ Wl, const float* __restrict__ Wr) {
    int b = blockIdx.x;
    if (b < 196) {                      // zero g_deg
        int i = b * 256 + threadIdx.x;
        if (i < N_NODES) g_deg[i] = 0;
    } else {                            // weight bf16 hi/lo split: 128 rows
        int j = b - 196;                // 0..127
        int k = threadIdx.x;            // 0..255
        float v = (k < 128) ? Wl[j * 128 + k] : Wr[j * 128 + (k - 128)];
        __nv_bfloat16 h = __float2bfloat16(v);
        g_w1hi[j * 256 + k] = h;
        g_w1lo[j * 256 + k] = __float2bfloat16(v - __bfloat162float(h));
    }
}

// ================= single-pass binning: 8 edges per thread =====================
#define EPT 8
#define PREP_BLOCKS ((N_EDGES + 256 * EPT - 1) / (256 * EPT))   // 391

__global__ void k_bin(const int* __restrict__ ei) {
    int t0 = (blockIdx.x * blockDim.x + threadIdx.x) * EPT;
    int srcs[EPT], dsts[EPT];
#pragma unroll
    for (int i = 0; i < EPT; ++i) {
        int e = t0 + i;
        srcs[i] = (e < N_EDGES) ? ei[e] : -1;
        dsts[i] = (e < N_EDGES) ? ei[N_EDGES + e] : -1;
    }
#pragma unroll
    for (int i = 0; i < EPT; ++i) {
        if ((unsigned)dsts[i] < (unsigned)N_NODES && (unsigned)srcs[i] < (unsigned)N_NODES) {
            int slot = atomicAdd(&g_deg[dsts[i]], 1);
            if (slot < CAP) g_bkt[(size_t)dsts[i] * CAP + slot] = srcs[i];
        }
    }
}

// ================= layer-1 aggregation: warp/node, unroll x4 ===================
__global__ void k_agg1(const float* __restrict__ x) {
    int w = (blockIdx.x * blockDim.x + threadIdx.x) >> 5;
    int lane = threadIdx.x & 31;
    if (w >= N_NODES) return;
    int deg = g_deg[w]; if (deg > CAP) deg = CAP;
    const int* bkt = g_bkt + (size_t)w * CAP;
    float4 acc = make_float4(0.f, 0.f, 0.f, 0.f);
    const float4* xv = (const float4*)x;
    int e = 0;
    for (; e + 4 <= deg; e += 4) {
        int s0 = bkt[e], s1 = bkt[e + 1], s2 = bkt[e + 2], s3 = bkt[e + 3];
        float4 v0 = xv[(size_t)s0 * 32 + lane];
        float4 v1 = xv[(size_t)s1 * 32 + lane];
        float4 v2 = xv[(size_t)s2 * 32 + lane];
        float4 v3 = xv[(size_t)s3 * 32 + lane];
        acc.x += (v0.x + v1.x) + (v2.x + v3.x);
        acc.y += (v0.y + v1.y) + (v2.y + v3.y);
        acc.z += (v0.z + v1.z) + (v2.z + v3.z);
        acc.w += (v0.w + v1.w) + (v2.w + v3.w);
    }
    for (; e < deg; ++e) {
        int s = bkt[e];
        float4 v = xv[(size_t)s * 32 + lane];
        acc.x += v.x; acc.y += v.y; acc.z += v.z; acc.w += v.w;
    }
    float inv = 1.0f / fmaxf((float)deg, 1.0f);
    float4* o = (float4*)g_agg;
    o[(size_t)w * 32 + lane] = make_float4(acc.x * inv, acc.y * inv, acc.z * inv, acc.w * inv);
}

// ================= fused layer1 GEMM (warp mma 4m x 2n) + layer2 self ==========
#define TSTRIDE 72            // bf16 elements per row (144 bytes)
#define TBYTES  (128 * TSTRIDE * 2)   // 18432 per tile

__global__ void __launch_bounds__(256, 2) k_gemm_mma(
    const float* __restrict__ x,
    const float* __restrict__ b1g,
    const float* __restrict__ W2l, const float* __restrict__ W2r,
    const float* __restrict__ b2,
    float* __restrict__ out)
{
    extern __shared__ char dynsm[];
    char* sAhi = dynsm;
    char* sAlo = dynsm + TBYTES;
    char* sBhi = dynsm + 2 * TBYTES;
    char* sBlo = dynsm + 3 * TBYTES;
    __shared__ float s_b1[128];
    __shared__ float s_w2[4][128];
    __shared__ float s_part[2][128][4];   // cross-warp-column epilogue combine

    const int tid = threadIdx.x;
    const int w = tid >> 5;
    const int lane = tid & 31;
    const int wm = w >> 1;          // 0..3  (m32 row group)
    const int wn = w & 1;           // 0..1  (n64 col group)
    const int m0 = blockIdx.x * 128;

    if (tid < 128) {
        s_b1[tid] = b1g[tid];
        s_w2[0][tid] = W2l[tid];
        s_w2[1][tid] = W2l[128 + tid];
        s_w2[2][tid] = W2r[tid];
        s_w2[3][tid] = W2r[128 + tid];
    }

    const uint32_t uAhi = smem_u32(sAhi), uAlo = smem_u32(sAlo);
    const uint32_t uBhi = smem_u32(sBhi), uBlo = smem_u32(sBlo);

    float acc[2][8][4];     // [am(m16)][n8 tile][frag]
#pragma unroll
    for (int am = 0; am < 2; ++am)
#pragma unroll
        for (int j = 0; j < 8; ++j)
#pragma unroll
            for (int q = 0; q < 4; ++q) acc[am][j][q] = 0.f;

    const int srow = tid >> 1;          // staging row 0..127
    const int shalf = tid & 1;          // 0/1 -> 32-element half

    for (int c = 0; c < 4; ++c) {
        if (c) __syncthreads();         // previous chunk's mma reads done
        // ---- stage A: fp32 -> bf16 hi/lo, 32 elems per thread
        {
            int node = m0 + srow;
            bool valid = node < N_NODES;
            const float* basep = (c < 2) ? g_agg : x;
            const float* srcp = basep + (size_t)(valid ? node : 0) * D
                                + (c & 1) * 64 + shalf * 32;
            char* dsth = sAhi + srow * 144 + shalf * 64;
            char* dstl = sAlo + srow * 144 + shalf * 64;
#pragma unroll
            for (int i = 0; i < 4; ++i) {
                float4 u = make_float4(0.f, 0.f, 0.f, 0.f);
                float4 v = make_float4(0.f, 0.f, 0.f, 0.f);
                if (valid) {
                    u = *(const float4*)(srcp + i * 8);
                    v = *(const float4*)(srcp + i * 8 + 4);
                }
                uint4 hv, lv;
                split8(u, v, hv, lv);
                *(uint4*)(dsth + i * 16) = hv;
                *(uint4*)(dstl + i * 16) = lv;
            }
        }
        // ---- stage B: copy pre-split bf16 weights
        {
            const char* ph = (const char*)g_w1hi + srow * 512 + c * 128 + shalf * 64;
            const char* pl = (const char*)g_w1lo + srow * 512 + c * 128 + shalf * 64;
            char* dsth = sBhi + srow * 144 + shalf * 64;
            char* dstl = sBlo + srow * 144 + shalf * 64;
#pragma unroll
            for (int i = 0; i < 4; ++i) {
                *(uint4*)(dsth + i * 16) = *(const uint4*)(ph + i * 16);
                *(uint4*)(dstl + i * 16) = *(const uint4*)(pl + i * 16);
            }
        }
        __syncthreads();

        // ---- compute: 4 k16-steps per chunk; warp tile m32 x n64
        const uint32_t lrow = lane & 15, lhalf = lane >> 4;
#pragma unroll
        for (int ks = 0; ks < 4; ++ks) {
            const uint32_t koff = (ks * 16 + lhalf * 8) * 2;   // bytes
            uint32_t ah[2][4], al[2][4];
            ldmx4(ah[0], uAhi + (wm * 32 + lrow) * 144 + koff);
            ldmx4(ah[1], uAhi + (wm * 32 + 16 + lrow) * 144 + koff);
            ldmx4(al[0], uAlo + (wm * 32 + lrow) * 144 + koff);
            ldmx4(al[1], uAlo + (wm * 32 + 16 + lrow) * 144 + koff);
#pragma unroll
            for (int nt = 0; nt < 4; ++nt) {
                uint32_t bh[4], bl[4];
                ldmx4(bh, uBhi + (wn * 64 + nt * 16 + lrow) * 144 + koff);
                ldmx4(bl, uBlo + (wn * 64 + nt * 16 + lrow) * 144 + koff);
#pragma unroll
                for (int am = 0; am < 2; ++am) {
                    mma16816(acc[am][2 * nt],     ah[am], bh[0], bh[2]);
                    mma16816(acc[am][2 * nt + 1], ah[am], bh[1], bh[3]);
                    mma16816(acc[am][2 * nt],     ah[am], bl[0], bl[2]);
                    mma16816(acc[am][2 * nt + 1], ah[am], bl[1], bl[3]);
                    mma16816(acc[am][2 * nt],     al[am], bh[0], bh[2]);
                    mma16816(acc[am][2 * nt + 1], al[am], bh[1], bh[3]);
                }
            }
        }
    }

    // ---- epilogue: bias + relu + partial layer2 dots over this warp's n64
    const int quad = lane >> 2;     // 0..7
    const int qt = lane & 3;        // 0..3
    float p[2][2][4];               // [am][row half 0:+0 1:+8][output]
#pragma unroll
    for (int am = 0; am < 2; ++am)
#pragma unroll
        for (int rh = 0; rh < 2; ++rh)
#pragma unroll
            for (int o = 0; o < 4; ++o) p[am][rh][o] = 0.f;

#pragma unroll
    for (int j = 0; j < 8; ++j) {
        int col0 = wn * 64 + j * 8 + qt * 2;
#pragma unroll
        for (int am = 0; am < 2; ++am) {
            float h00 = fmaxf(acc[am][j][0] + s_b1[col0],     0.f);
            float h01 = fmaxf(acc[am][j][1] + s_b1[col0 + 1], 0.f);
            float h10 = fmaxf(acc[am][j][2] + s_b1[col0],     0.f);
            float h11 = fmaxf(acc[am][j][3] + s_b1[col0 + 1], 0.f);
#pragma unroll
            for (int o = 0; o < 4; ++o) {
                p[am][0][o] += h00 * s_w2[o][col0] + h01 * s_w2[o][col0 + 1];
                p[am][1][o] += h10 * s_w2[o][col0] + h11 * s_w2[o][col0 + 1];
            }
        }
    }
#pragma unroll
    for (int m = 1; m <= 2; m <<= 1)
#pragma unroll
        for (int am = 0; am < 2; ++am)
#pragma unroll
            for (int rh = 0; rh < 2; ++rh)
#pragma unroll
                for (int o = 0; o < 4; ++o)
                    p[am][rh][o] += __shfl_xor_sync(0xFFFFFFFFu, p[am][rh][o], m);

    if (qt == 0) {
#pragma unroll
        for (int am = 0; am < 2; ++am)
#pragma unroll
            for (int rh = 0; rh < 2; ++rh) {
                int rl = wm * 32 + am * 16 + rh * 8 + quad;
#pragma unroll
                for (int o = 0; o < 4; ++o) s_part[wn][rl][o] = p[am][rh][o];
            }
    }
    __syncthreads();

    if (tid < 128) {
        int row = m0 + tid;
        if (row < N_NODES) {
            float v0 = s_part[0][tid][0] + s_part[1][tid][0];
            float v1 = s_part[0][tid][1] + s_part[1][tid][1];
            float v2 = s_part[0][tid][2] + s_part[1][tid][2];
            float v3 = s_part[0][tid][3] + s_part[1][tid][3];
            *(float2*)(g_y2 + (size_t)row * 2) = make_float2(v0, v1);
            *(float2*)(out + (size_t)row * 2) = make_float2(v2 + b2[0], v3 + b2[1]);
        }
    }
}

// ================= layer-2 aggregation of y2 (8 bytes/edge) ====================
__global__ void k_agg2(float* __restrict__ out) {
    int v = (blockIdx.x * blockDim.x + threadIdx.x) >> 5;
    int lane = threadIdx.x & 31;
    if (v >= N_NODES) return;
    int deg = g_deg[v]; if (deg > CAP) deg = CAP;
    const int* bkt = g_bkt + (size_t)v * CAP;
    float a0 = 0.f, a1 = 0.f;
    for (int e = lane; e < deg; e += 32) {
        int s = bkt[e];
        float2 y = ((const float2*)g_y2)[s];
        a0 += y.x; a1 += y.y;
    }
#pragma unroll
    for (int o = 16; o > 0; o >>= 1) {
        a0 += __shfl_xor_sync(0xFFFFFFFFu, a0, o);
        a1 += __shfl_xor_sync(0xFFFFFFFFu, a1, o);
    }
    if (lane == 0) {
        float inv = 1.0f / fmaxf((float)deg, 1.0f);
        out[v * 2 + 0] += a0 * inv;
        out[v * 2 + 1] += a1 * inv;
    }
}

// ================= launch ======================================================
extern "C" void kernel_launch(void* const* d_in, const int* in_sizes, int n_in,
                              void* d_out, int out_size)
{
    const float* x    = (const float*)d_in[0];
    const int*   ei   = (const int*)d_in[1];
    const float* W1l  = (const float*)d_in[2];
    const float* W1r  = (const float*)d_in[3];
    const float* b1   = (const float*)d_in[4];
    const float* W2l  = (const float*)d_in[5];
    const float* W2r  = (const float*)d_in[6];
    const float* b2   = (const float*)d_in[7];
    float* out = (float*)d_out;

    const int DSMEM = 4 * TBYTES;   // 73728 B
    cudaFuncSetAttribute(k_gemm_mma, cudaFuncAttributeMaxDynamicSharedMemorySize, DSMEM);

    k_zero_prep<<<196 + 128, 256>>>(W1l, W1r);
    k_bin<<<PREP_BLOCKS, 256>>>(ei);
    k_agg1<<<(N_NODES * 32 + 255) / 256, 256>>>(x);
    k_gemm_mma<<<(N_NODES + 127) / 128, 256, DSMEM>>>(x, b1, W2l, W2r, b2, out);
    k_agg2<<<(N_NODES * 32 + 255) / 256, 256>>>(out);
}

// round 13
// speedup vs baseline: 2.5771x; 1.0606x over previous
#include <cuda_runtime.h>
#include <cuda_bf16.h>
#include <cuda_fp16.h>
#include <cstdint>

#define N_NODES 50000
#define N_EDGES 800000
#define D 128
#define CAP 128            // bucket capacity per dst (Poisson(16): overflow ~1e-60)

// ================= scratch =====================================================
__device__ __align__(16) int    g_deg[N_NODES];
__device__ __align__(16) int    g_bkt[(size_t)N_NODES * CAP];  // src buckets
__device__ __align__(16) float  g_y2[(size_t)N_NODES * 2];     // h @ W2_l^T
__device__ __align__(16) __half g_ahi[(size_t)N_NODES * 256];  // A=[agg|x] fp16 hi
__device__ __align__(16) __half g_alo[(size_t)N_NODES * 256];  // A residual fp16
__device__ __align__(16) __half g_w1h[128 * 256];              // [Wl|Wr] fp16

// ================= helpers =====================================================
__device__ __forceinline__ uint32_t smem_u32(const void* p) {
    uint32_t a;
    asm("{ .reg .u64 t; cvta.to.shared.u64 t, %1; cvt.u32.u64 %0, t; }"
        : "=r"(a) : "l"(p));
    return a;
}

__device__ __forceinline__ void ldmx4(uint32_t* r, uint32_t addr) {
    asm volatile("ldmatrix.sync.aligned.m8n8.x4.shared.b16 {%0,%1,%2,%3}, [%4];"
        : "=r"(r[0]), "=r"(r[1]), "=r"(r[2]), "=r"(r[3]) : "r"(addr));
}

__device__ __forceinline__ void mma16816(float* d, const uint32_t* a,
                                         uint32_t b0, uint32_t b1) {
    asm volatile("mma.sync.aligned.m16n8k16.row.col.f32.f16.f16.f32 "
        "{%0,%1,%2,%3}, {%4,%5,%6,%7}, {%8,%9}, {%0,%1,%2,%3};"
        : "+f"(d[0]), "+f"(d[1]), "+f"(d[2]), "+f"(d[3])
        : "r"(a[0]), "r"(a[1]), "r"(a[2]), "r"(a[3]), "r"(b0), "r"(b1));
}

// ================= prep: zero deg + W fp16 + x fp16-split (merged) =============
// grid: [0,196) zero g_deg; [196,324) W rows; [324, 324+12500) x split (2 el/thr)
__global__ void k_zero_prep(const float* __restrict__ Wl, const float* __restrict__ Wr,
                            const float* __restrict__ x) {
    int b = blockIdx.x;
    if (b < 196) {
        int i = b * 256 + threadIdx.x;
        if (i < N_NODES) g_deg[i] = 0;
    } else if (b < 324) {
        int j = b - 196;                // 0..127
        int k = threadIdx.x;            // 0..255
        float v = (k < 128) ? Wl[j * 128 + k] : Wr[j * 128 + (k - 128)];
        g_w1h[j * 256 + k] = __float2half(v);
    } else {
        // x split: pair index over 50000*128/2
        long long p = (long long)(b - 324) * 256 + threadIdx.x;
        long long idx = p * 2;
        if (idx < (long long)N_NODES * 128) {
            int node = (int)(idx >> 7);
            int col = (int)(idx & 127);
            float v0 = x[(size_t)node * 128 + col];
            float v1 = x[(size_t)node * 128 + col + 1];
            __half h0 = __float2half(v0), h1 = __float2half(v1);
            __half l0 = __float2half(v0 - __half2float(h0));
            __half l1 = __float2half(v1 - __half2float(h1));
            __half2* ph = (__half2*)(g_ahi + (size_t)node * 256 + 128 + col);
            __half2* pl = (__half2*)(g_alo + (size_t)node * 256 + 128 + col);
            *ph = __halves2half2(h0, h1);
            *pl = __halves2half2(l0, l1);
        }
    }
}

// ================= single-pass binning: 8 edges per thread =====================
#define EPT 8
#define PREP_BLOCKS ((N_EDGES + 256 * EPT - 1) / (256 * EPT))   // 391

__global__ void k_bin(const int* __restrict__ ei) {
    int t0 = (blockIdx.x * blockDim.x + threadIdx.x) * EPT;
    int srcs[EPT], dsts[EPT];
#pragma unroll
    for (int i = 0; i < EPT; ++i) {
        int e = t0 + i;
        srcs[i] = (e < N_EDGES) ? ei[e] : -1;
        dsts[i] = (e < N_EDGES) ? ei[N_EDGES + e] : -1;
    }
#pragma unroll
    for (int i = 0; i < EPT; ++i) {
        if ((unsigned)dsts[i] < (unsigned)N_NODES && (unsigned)srcs[i] < (unsigned)N_NODES) {
            int slot = atomicAdd(&g_deg[dsts[i]], 1);
            if (slot < CAP) g_bkt[(size_t)dsts[i] * CAP + slot] = srcs[i];
        }
    }
}

// ================= layer-1 aggregation -> fp16 hi/lo split output ==============
__global__ void k_agg1(const float* __restrict__ x) {
    int w = (blockIdx.x * blockDim.x + threadIdx.x) >> 5;
    int lane = threadIdx.x & 31;
    if (w >= N_NODES) return;
    int deg = g_deg[w]; if (deg > CAP) deg = CAP;
    const int* bkt = g_bkt + (size_t)w * CAP;
    float4 acc = make_float4(0.f, 0.f, 0.f, 0.f);
    const float4* xv = (const float4*)x;
    int e = 0;
    for (; e + 4 <= deg; e += 4) {
        int s0 = bkt[e], s1 = bkt[e + 1], s2 = bkt[e + 2], s3 = bkt[e + 3];
        float4 v0 = xv[(size_t)s0 * 32 + lane];
        float4 v1 = xv[(size_t)s1 * 32 + lane];
        float4 v2 = xv[(size_t)s2 * 32 + lane];
        float4 v3 = xv[(size_t)s3 * 32 + lane];
        acc.x += (v0.x + v1.x) + (v2.x + v3.x);
        acc.y += (v0.y + v1.y) + (v2.y + v3.y);
        acc.z += (v0.z + v1.z) + (v2.z + v3.z);
        acc.w += (v0.w + v1.w) + (v2.w + v3.w);
    }
    for (; e < deg; ++e) {
        int s = bkt[e];
        float4 v = xv[(size_t)s * 32 + lane];
        acc.x += v.x; acc.y += v.y; acc.z += v.z; acc.w += v.w;
    }
    float inv = 1.0f / fmaxf((float)deg, 1.0f);
    float f[4] = {acc.x * inv, acc.y * inv, acc.z * inv, acc.w * inv};
    __half h[4], l[4];
#pragma unroll
    for (int i = 0; i < 4; ++i) {
        h[i] = __float2half(f[i]);
        l[i] = __float2half(f[i] - __half2float(h[i]));
    }
    *(__half2*)(g_ahi + (size_t)w * 256 + lane * 4)     = __halves2half2(h[0], h[1]);
    *(__half2*)(g_ahi + (size_t)w * 256 + lane * 4 + 2) = __halves2half2(h[2], h[3]);
    *(__half2*)(g_alo + (size_t)w * 256 + lane * 4)     = __halves2half2(l[0], l[1]);
    *(__half2*)(g_alo + (size_t)w * 256 + lane * 4 + 2) = __halves2half2(l[2], l[3]);
}

// ================= fused layer1 GEMM (fp16 mma, 2-pass) + layer2 self ==========
#define TSTRIDE_B 144         // bytes per smem tile row (64 fp16 data + pad)
#define TBYTES  (128 * TSTRIDE_B)     // 18432 per tile

__global__ void __launch_bounds__(256, 2) k_gemm_mma(
    const float* __restrict__ b1g,
    const float* __restrict__ W2l, const float* __restrict__ W2r,
    const float* __restrict__ b2,
    float* __restrict__ out)
{
    extern __shared__ char dynsm[];
    char* sAhi = dynsm;
    char* sAlo = dynsm + TBYTES;
    char* sBh  = dynsm + 2 * TBYTES;
    __shared__ float s_b1[128];
    __shared__ float s_w2[4][128];
    __shared__ float s_part[2][128][4];   // cross-warp-column epilogue combine

    const int tid = threadIdx.x;
    const int w = tid >> 5;
    const int lane = tid & 31;
    const int wm = w >> 1;          // 0..3  (m32 row group)
    const int wn = w & 1;           // 0..1  (n64 col group)
    const int m0 = blockIdx.x * 128;

    if (tid < 128) {
        s_b1[tid] = b1g[tid];
        s_w2[0][tid] = W2l[tid];
        s_w2[1][tid] = W2l[128 + tid];
        s_w2[2][tid] = W2r[tid];
        s_w2[3][tid] = W2r[128 + tid];
    }

    const uint32_t uAhi = smem_u32(sAhi), uAlo = smem_u32(sAlo);
    const uint32_t uBh = smem_u32(sBh);

    float acc[2][8][4];     // [am(m16)][n8 tile][frag]
#pragma unroll
    for (int am = 0; am < 2; ++am)
#pragma unroll
        for (int j = 0; j < 8; ++j)
#pragma unroll
            for (int q = 0; q < 4; ++q) acc[am][j][q] = 0.f;

    const int srow = tid >> 1;          // staging row 0..127
    const int shalf = tid & 1;          // 0/1 -> 64B half of 128B chunk row

    for (int c = 0; c < 4; ++c) {
        if (c) __syncthreads();         // previous chunk's mma reads done
        // ---- stage A hi/lo + B: pure 16B copies (pre-split fp16)
        {
            int node = m0 + srow;
            bool valid = node < N_NODES;
            const char* pah = (const char*)g_ahi + (size_t)(valid ? node : 0) * 512
                              + c * 128 + shalf * 64;
            const char* pal = (const char*)g_alo + (size_t)(valid ? node : 0) * 512
                              + c * 128 + shalf * 64;
            char* dh = sAhi + srow * TSTRIDE_B + shalf * 64;
            char* dl = sAlo + srow * TSTRIDE_B + shalf * 64;
            const uint4 z = make_uint4(0, 0, 0, 0);
#pragma unroll
            for (int i = 0; i < 4; ++i) {
                *(uint4*)(dh + i * 16) = valid ? *(const uint4*)(pah + i * 16) : z;
                *(uint4*)(dl + i * 16) = valid ? *(const uint4*)(pal + i * 16) : z;
            }
            const char* pb = (const char*)g_w1h + srow * 512 + c * 128 + shalf * 64;
            char* db = sBh + srow * TSTRIDE_B + shalf * 64;
#pragma unroll
            for (int i = 0; i < 4; ++i)
                *(uint4*)(db + i * 16) = *(const uint4*)(pb + i * 16);
        }
        __syncthreads();

        // ---- compute: 4 k16-steps per chunk; warp tile m32 x n64; 2 passes
        const uint32_t lrow = lane & 15, lhalf = lane >> 4;
#pragma unroll
        for (int ks = 0; ks < 4; ++ks) {
            const uint32_t koff = (ks * 16 + lhalf * 8) * 2;   // bytes
            uint32_t ah[2][4], al[2][4];
            ldmx4(ah[0], uAhi + (wm * 32 + lrow) * TSTRIDE_B + koff);
            ldmx4(ah[1], uAhi + (wm * 32 + 16 + lrow) * TSTRIDE_B + koff);
            ldmx4(al[0], uAlo + (wm * 32 + lrow) * TSTRIDE_B + koff);
            ldmx4(al[1], uAlo + (wm * 32 + 16 + lrow) * TSTRIDE_B + koff);
#pragma unroll
            for (int nt = 0; nt < 4; ++nt) {
                uint32_t bh[4];
                ldmx4(bh, uBh + (wn * 64 + nt * 16 + lrow) * TSTRIDE_B + koff);
#pragma unroll
                for (int am = 0; am < 2; ++am) {
                    mma16816(acc[am][2 * nt],     ah[am], bh[0], bh[2]);
                    mma16816(acc[am][2 * nt + 1], ah[am], bh[1], bh[3]);
                    mma16816(acc[am][2 * nt],     al[am], bh[0], bh[2]);
                    mma16816(acc[am][2 * nt + 1], al[am], bh[1], bh[3]);
                }
            }
        }
    }

    // ---- epilogue: bias + relu + partial layer2 dots over this warp's n64
    const int quad = lane >> 2;     // 0..7
    const int qt = lane & 3;        // 0..3
    float p[2][2][4];               // [am][row half 0:+0 1:+8][output]
#pragma unroll
    for (int am = 0; am < 2; ++am)
#pragma unroll
        for (int rh = 0; rh < 2; ++rh)
#pragma unroll
            for (int o = 0; o < 4; ++o) p[am][rh][o] = 0.f;

#pragma unroll
    for (int j = 0; j < 8; ++j) {
        int col0 = wn * 64 + j * 8 + qt * 2;
#pragma unroll
        for (int am = 0; am < 2; ++am) {
            float h00 = fmaxf(acc[am][j][0] + s_b1[col0],     0.f);
            float h01 = fmaxf(acc[am][j][1] + s_b1[col0 + 1], 0.f);
            float h10 = fmaxf(acc[am][j][2] + s_b1[col0],     0.f);
            float h11 = fmaxf(acc[am][j][3] + s_b1[col0 + 1], 0.f);
#pragma unroll
            for (int o = 0; o < 4; ++o) {
                p[am][0][o] += h00 * s_w2[o][col0] + h01 * s_w2[o][col0 + 1];
                p[am][1][o] += h10 * s_w2[o][col0] + h11 * s_w2[o][col0 + 1];
            }
        }
    }
#pragma unroll
    for (int m = 1; m <= 2; m <<= 1)
#pragma unroll
        for (int am = 0; am < 2; ++am)
#pragma unroll
            for (int rh = 0; rh < 2; ++rh)
#pragma unroll
                for (int o = 0; o < 4; ++o)
                    p[am][rh][o] += __shfl_xor_sync(0xFFFFFFFFu, p[am][rh][o], m);

    if (qt == 0) {
#pragma unroll
        for (int am = 0; am < 2; ++am)
#pragma unroll
            for (int rh = 0; rh < 2; ++rh) {
                int rl = wm * 32 + am * 16 + rh * 8 + quad;
#pragma unroll
                for (int o = 0; o < 4; ++o) s_part[wn][rl][o] = p[am][rh][o];
            }
    }
    __syncthreads();

    if (tid < 128) {
        int row = m0 + tid;
        if (row < N_NODES) {
            float v0 = s_part[0][tid][0] + s_part[1][tid][0];
            float v1 = s_part[0][tid][1] + s_part[1][tid][1];
            float v2 = s_part[0][tid][2] + s_part[1][tid][2];
            float v3 = s_part[0][tid][3] + s_part[1][tid][3];
            *(float2*)(g_y2 + (size_t)row * 2) = make_float2(v0, v1);
            *(float2*)(out + (size_t)row * 2) = make_float2(v2 + b2[0], v3 + b2[1]);
        }
    }
}

// ================= layer-2 aggregation of y2 (8 bytes/edge) ====================
__global__ void k_agg2(float* __restrict__ out) {
    int v = (blockIdx.x * blockDim.x + threadIdx.x) >> 5;
    int lane = threadIdx.x & 31;
    if (v >= N_NODES) return;
    int deg = g_deg[v]; if (deg > CAP) deg = CAP;
    const int* bkt = g_bkt + (size_t)v * CAP;
    float a0 = 0.f, a1 = 0.f;
    for (int e = lane; e < deg; e += 32) {
        int s = bkt[e];
        float2 y = ((const float2*)g_y2)[s];
        a0 += y.x; a1 += y.y;
    }
#pragma unroll
    for (int o = 16; o > 0; o >>= 1) {
        a0 += __shfl_xor_sync(0xFFFFFFFFu, a0, o);
        a1 += __shfl_xor_sync(0xFFFFFFFFu, a1, o);
    }
    if (lane == 0) {
        float inv = 1.0f / fmaxf((float)deg, 1.0f);
        out[v * 2 + 0] += a0 * inv;
        out[v * 2 + 1] += a1 * inv;
    }
}

// ================= launch ======================================================
extern "C" void kernel_launch(void* const* d_in, const int* in_sizes, int n_in,
                              void* d_out, int out_size)
{
    const float* x    = (const float*)d_in[0];
    const int*   ei   = (const int*)d_in[1];
    const float* W1l  = (const float*)d_in[2];
    const float* W1r  = (const float*)d_in[3];
    const float* b1   = (const float*)d_in[4];
    const float* W2l  = (const float*)d_in[5];
    const float* W2r  = (const float*)d_in[6];
    const float* b2   = (const float*)d_in[7];
    float* out = (float*)d_out;

    const int DSMEM = 3 * TBYTES;   // 55296 B
    cudaFuncSetAttribute(k_gemm_mma, cudaFuncAttributeMaxDynamicSharedMemorySize, DSMEM);

    const int XBLOCKS = (N_NODES * 128 / 2 + 255) / 256;   // 12500
    k_zero_prep<<<196 + 128 + XBLOCKS, 256>>>(W1l, W1r, x);
    k_bin<<<PREP_BLOCKS, 256>>>(ei);
    k_agg1<<<(N_NODES * 32 + 255) / 256, 256>>>(x);
    k_gemm_mma<<<(N_NODES + 127) / 128, 256, DSMEM>>>(b1, W2l, W2r, b2, out);
    k_agg2<<<(N_NODES * 32 + 255) / 256, 256>>>(out);
}

// round 14
// speedup vs baseline: 2.8011x; 1.0869x over previous
#include <cuda_runtime.h>
#include <cuda_bf16.h>
#include <cuda_fp16.h>
#include <cstdint>

#define N_NODES 50000
#define N_EDGES 800000
#define D 128
#define CAP 128            // bucket capacity per dst (Poisson(16): overflow ~1e-60)

// ================= scratch =====================================================
__device__ __align__(16) int    g_deg[N_NODES];
__device__ __align__(16) int    g_bkt[(size_t)N_NODES * CAP];  // src buckets
__device__ __align__(16) float  g_y2[(size_t)N_NODES * 2];     // h @ W2_l^T
__device__ __align__(16) __half g_ahi[(size_t)N_NODES * 256];  // A=[agg|x] fp16 hi
__device__ __align__(16) __half g_alo[(size_t)N_NODES * 256];  // A residual fp16
__device__ __align__(16) __half g_w1h[128 * 256];              // [Wl|Wr] fp16

// ================= helpers =====================================================
__device__ __forceinline__ uint32_t smem_u32(const void* p) {
    uint32_t a;
    asm("{ .reg .u64 t; cvta.to.shared.u64 t, %1; cvt.u32.u64 %0, t; }"
        : "=r"(a) : "l"(p));
    return a;
}

__device__ __forceinline__ void ldmx4(uint32_t* r, uint32_t addr) {
    asm volatile("ldmatrix.sync.aligned.m8n8.x4.shared.b16 {%0,%1,%2,%3}, [%4];"
        : "=r"(r[0]), "=r"(r[1]), "=r"(r[2]), "=r"(r[3]) : "r"(addr));
}

__device__ __forceinline__ void mma16816(float* d, const uint32_t* a,
                                         uint32_t b0, uint32_t b1) {
    asm volatile("mma.sync.aligned.m16n8k16.row.col.f32.f16.f16.f32 "
        "{%0,%1,%2,%3}, {%4,%5,%6,%7}, {%8,%9}, {%0,%1,%2,%3};"
        : "+f"(d[0]), "+f"(d[1]), "+f"(d[2]), "+f"(d[3])
        : "r"(a[0]), "r"(a[1]), "r"(a[2]), "r"(a[3]), "r"(b0), "r"(b1));
}

// ================= prep: zero deg + W fp16 + x fp16-split (merged) =============
// grid: [0,196) zero g_deg; [196,324) W rows; [324, 324+12500) x split (2 el/thr)
__global__ void k_zero_prep(const float* __restrict__ Wl, const float* __restrict__ Wr,
                            const float* __restrict__ x) {
    int b = blockIdx.x;
    if (b < 196) {
        int i = b * 256 + threadIdx.x;
        if (i < N_NODES) g_deg[i] = 0;
    } else if (b < 324) {
        int j = b - 196;                // 0..127
        int k = threadIdx.x;            // 0..255
        float v = (k < 128) ? Wl[j * 128 + k] : Wr[j * 128 + (k - 128)];
        g_w1h[j * 256 + k] = __float2half(v);
    } else {
        // x split: pair index over 50000*128/2
        long long p = (long long)(b - 324) * 256 + threadIdx.x;
        long long idx = p * 2;
        if (idx < (long long)N_NODES * 128) {
            int node = (int)(idx >> 7);
            int col = (int)(idx & 127);
            float v0 = x[(size_t)node * 128 + col];
            float v1 = x[(size_t)node * 128 + col + 1];
            __half h0 = __float2half(v0), h1 = __float2half(v1);
            __half l0 = __float2half(v0 - __half2float(h0));
            __half l1 = __float2half(v1 - __half2float(h1));
            __half2* ph = (__half2*)(g_ahi + (size_t)node * 256 + 128 + col);
            __half2* pl = (__half2*)(g_alo + (size_t)node * 256 + 128 + col);
            *ph = __halves2half2(h0, h1);
            *pl = __halves2half2(l0, l1);
        }
    }
}

// ================= single-pass binning: 8 edges per thread =====================
#define EPT 8
#define PREP_BLOCKS ((N_EDGES + 256 * EPT - 1) / (256 * EPT))   // 391

__global__ void k_bin(const int* __restrict__ ei) {
    int t0 = (blockIdx.x * blockDim.x + threadIdx.x) * EPT;
    int srcs[EPT], dsts[EPT];
#pragma unroll
    for (int i = 0; i < EPT; ++i) {
        int e = t0 + i;
        srcs[i] = (e < N_EDGES) ? ei[e] : -1;
        dsts[i] = (e < N_EDGES) ? ei[N_EDGES + e] : -1;
    }
#pragma unroll
    for (int i = 0; i < EPT; ++i) {
        if ((unsigned)dsts[i] < (unsigned)N_NODES && (unsigned)srcs[i] < (unsigned)N_NODES) {
            int slot = atomicAdd(&g_deg[dsts[i]], 1);
            if (slot < CAP) g_bkt[(size_t)dsts[i] * CAP + slot] = srcs[i];
        }
    }
}

// ================= layer-1 aggregation: gather fp16 x (256B/row) ===============
// reads x-hi from g_ahi cols 128..255 (written by k_zero_prep); accumulates fp32;
// writes agg as fp16 hi/lo into g_ahi/g_alo cols 0..127.
__global__ void k_agg1() {
    int w = (blockIdx.x * blockDim.x + threadIdx.x) >> 5;
    int lane = threadIdx.x & 31;
    if (w >= N_NODES) return;
    int deg = g_deg[w]; if (deg > CAP) deg = CAP;
    const int* bkt = g_bkt + (size_t)w * CAP;
    float a0 = 0.f, a1 = 0.f, a2 = 0.f, a3 = 0.f;
    int e = 0;
    for (; e + 4 <= deg; e += 4) {
        int s0 = bkt[e], s1 = bkt[e + 1], s2 = bkt[e + 2], s3 = bkt[e + 3];
        uint2 u0 = ((const uint2*)(g_ahi + (size_t)s0 * 256 + 128))[lane];
        uint2 u1 = ((const uint2*)(g_ahi + (size_t)s1 * 256 + 128))[lane];
        uint2 u2 = ((const uint2*)(g_ahi + (size_t)s2 * 256 + 128))[lane];
        uint2 u3 = ((const uint2*)(g_ahi + (size_t)s3 * 256 + 128))[lane];
#pragma unroll
        for (int q = 0; q < 4; ++q) {
            uint2 u = (q == 0) ? u0 : (q == 1) ? u1 : (q == 2) ? u2 : u3;
            float2 f0 = __half22float2(*(__half2*)&u.x);
            float2 f1 = __half22float2(*(__half2*)&u.y);
            a0 += f0.x; a1 += f0.y; a2 += f1.x; a3 += f1.y;
        }
    }
    for (; e < deg; ++e) {
        int s = bkt[e];
        uint2 u = ((const uint2*)(g_ahi + (size_t)s * 256 + 128))[lane];
        float2 f0 = __half22float2(*(__half2*)&u.x);
        float2 f1 = __half22float2(*(__half2*)&u.y);
        a0 += f0.x; a1 += f0.y; a2 += f1.x; a3 += f1.y;
    }
    float inv = 1.0f / fmaxf((float)deg, 1.0f);
    float f[4] = {a0 * inv, a1 * inv, a2 * inv, a3 * inv};
    __half h[4], l[4];
#pragma unroll
    for (int i = 0; i < 4; ++i) {
        h[i] = __float2half(f[i]);
        l[i] = __float2half(f[i] - __half2float(h[i]));
    }
    *(__half2*)(g_ahi + (size_t)w * 256 + lane * 4)     = __halves2half2(h[0], h[1]);
    *(__half2*)(g_ahi + (size_t)w * 256 + lane * 4 + 2) = __halves2half2(h[2], h[3]);
    *(__half2*)(g_alo + (size_t)w * 256 + lane * 4)     = __halves2half2(l[0], l[1]);
    *(__half2*)(g_alo + (size_t)w * 256 + lane * 4 + 2) = __halves2half2(l[2], l[3]);
}

// ================= fused layer1 GEMM (fp16 mma, 2-pass) + layer2 self ==========
#define TSTRIDE_B 144         // bytes per smem tile row (64 fp16 data + pad)
#define TBYTES  (128 * TSTRIDE_B)     // 18432 per tile

__global__ void __launch_bounds__(256, 2) k_gemm_mma(
    const float* __restrict__ b1g,
    const float* __restrict__ W2l, const float* __restrict__ W2r,
    const float* __restrict__ b2,
    float* __restrict__ out)
{
    extern __shared__ char dynsm[];
    char* sAhi = dynsm;
    char* sAlo = dynsm + TBYTES;
    char* sBh  = dynsm + 2 * TBYTES;
    __shared__ float s_b1[128];
    __shared__ float s_w2[4][128];
    __shared__ float s_part[2][128][4];   // cross-warp-column epilogue combine

    const int tid = threadIdx.x;
    const int w = tid >> 5;
    const int lane = tid & 31;
    const int wm = w >> 1;          // 0..3  (m32 row group)
    const int wn = w & 1;           // 0..1  (n64 col group)
    const int m0 = blockIdx.x * 128;

    if (tid < 128) {
        s_b1[tid] = b1g[tid];
        s_w2[0][tid] = W2l[tid];
        s_w2[1][tid] = W2l[128 + tid];
        s_w2[2][tid] = W2r[tid];
        s_w2[3][tid] = W2r[128 + tid];
    }

    const uint32_t uAhi = smem_u32(sAhi), uAlo = smem_u32(sAlo);
    const uint32_t uBh = smem_u32(sBh);

    float acc[2][8][4];     // [am(m16)][n8 tile][frag]
#pragma unroll
    for (int am = 0; am < 2; ++am)
#pragma unroll
        for (int j = 0; j < 8; ++j)
#pragma unroll
            for (int q = 0; q < 4; ++q) acc[am][j][q] = 0.f;

    const int srow = tid >> 1;          // staging row 0..127
    const int shalf = tid & 1;          // 0/1 -> 64B half of 128B chunk row

    for (int c = 0; c < 4; ++c) {
        if (c) __syncthreads();         // previous chunk's mma reads done
        // ---- stage A hi/lo + B: pure 16B copies (pre-split fp16)
        {
            int node = m0 + srow;
            bool valid = node < N_NODES;
            const char* pah = (const char*)g_ahi + (size_t)(valid ? node : 0) * 512
                              + c * 128 + shalf * 64;
            const char* pal = (const char*)g_alo + (size_t)(valid ? node : 0) * 512
                              + c * 128 + shalf * 64;
            char* dh = sAhi + srow * TSTRIDE_B + shalf * 64;
            char* dl = sAlo + srow * TSTRIDE_B + shalf * 64;
            const uint4 z = make_uint4(0, 0, 0, 0);
#pragma unroll
            for (int i = 0; i < 4; ++i) {
                *(uint4*)(dh + i * 16) = valid ? *(const uint4*)(pah + i * 16) : z;
                *(uint4*)(dl + i * 16) = valid ? *(const uint4*)(pal + i * 16) : z;
            }
            const char* pb = (const char*)g_w1h + srow * 512 + c * 128 + shalf * 64;
            char* db = sBh + srow * TSTRIDE_B + shalf * 64;
#pragma unroll
            for (int i = 0; i < 4; ++i)
                *(uint4*)(db + i * 16) = *(const uint4*)(pb + i * 16);
        }
        __syncthreads();

        // ---- compute: 4 k16-steps per chunk; warp tile m32 x n64; 2 passes
        const uint32_t lrow = lane & 15, lhalf = lane >> 4;
#pragma unroll
        for (int ks = 0; ks < 4; ++ks) {
            const uint32_t koff = (ks * 16 + lhalf * 8) * 2;   // bytes
            uint32_t ah[2][4], al[2][4];
            ldmx4(ah[0], uAhi + (wm * 32 + lrow) * TSTRIDE_B + koff);
            ldmx4(ah[1], uAhi + (wm * 32 + 16 + lrow) * TSTRIDE_B + koff);
            ldmx4(al[0], uAlo + (wm * 32 + lrow) * TSTRIDE_B + koff);
            ldmx4(al[1], uAlo + (wm * 32 + 16 + lrow) * TSTRIDE_B + koff);
#pragma unroll
            for (int nt = 0; nt < 4; ++nt) {
                uint32_t bh[4];
                ldmx4(bh, uBh + (wn * 64 + nt * 16 + lrow) * TSTRIDE_B + koff);
#pragma unroll
                for (int am = 0; am < 2; ++am) {
                    mma16816(acc[am][2 * nt],     ah[am], bh[0], bh[2]);
                    mma16816(acc[am][2 * nt + 1], ah[am], bh[1], bh[3]);
                    mma16816(acc[am][2 * nt],     al[am], bh[0], bh[2]);
                    mma16816(acc[am][2 * nt + 1], al[am], bh[1], bh[3]);
                }
            }
        }
    }

    // ---- epilogue: bias + relu + partial layer2 dots over this warp's n64
    const int quad = lane >> 2;     // 0..7
    const int qt = lane & 3;        // 0..3
    float p[2][2][4];               // [am][row half 0:+0 1:+8][output]
#pragma unroll
    for (int am = 0; am < 2; ++am)
#pragma unroll
        for (int rh = 0; rh < 2; ++rh)
#pragma unroll
            for (int o = 0; o < 4; ++o) p[am][rh][o] = 0.f;

#pragma unroll
    for (int j = 0; j < 8; ++j) {
        int col0 = wn * 64 + j * 8 + qt * 2;
#pragma unroll
        for (int am = 0; am < 2; ++am) {
            float h00 = fmaxf(acc[am][j][0] + s_b1[col0],     0.f);
            float h01 = fmaxf(acc[am][j][1] + s_b1[col0 + 1], 0.f);
            float h10 = fmaxf(acc[am][j][2] + s_b1[col0],     0.f);
            float h11 = fmaxf(acc[am][j][3] + s_b1[col0 + 1], 0.f);
#pragma unroll
            for (int o = 0; o < 4; ++o) {
                p[am][0][o] += h00 * s_w2[o][col0] + h01 * s_w2[o][col0 + 1];
                p[am][1][o] += h10 * s_w2[o][col0] + h11 * s_w2[o][col0 + 1];
            }
        }
    }
#pragma unroll
    for (int m = 1; m <= 2; m <<= 1)
#pragma unroll
        for (int am = 0; am < 2; ++am)
#pragma unroll
            for (int rh = 0; rh < 2; ++rh)
#pragma unroll
                for (int o = 0; o < 4; ++o)
                    p[am][rh][o] += __shfl_xor_sync(0xFFFFFFFFu, p[am][rh][o], m);

    if (qt == 0) {
#pragma unroll
        for (int am = 0; am < 2; ++am)
#pragma unroll
            for (int rh = 0; rh < 2; ++rh) {
                int rl = wm * 32 + am * 16 + rh * 8 + quad;
#pragma unroll
                for (int o = 0; o < 4; ++o) s_part[wn][rl][o] = p[am][rh][o];
            }
    }
    __syncthreads();

    if (tid < 128) {
        int row = m0 + tid;
        if (row < N_NODES) {
            float v0 = s_part[0][tid][0] + s_part[1][tid][0];
            float v1 = s_part[0][tid][1] + s_part[1][tid][1];
            float v2 = s_part[0][tid][2] + s_part[1][tid][2];
            float v3 = s_part[0][tid][3] + s_part[1][tid][3];
            *(float2*)(g_y2 + (size_t)row * 2) = make_float2(v0, v1);
            *(float2*)(out + (size_t)row * 2) = make_float2(v2 + b2[0], v3 + b2[1]);
        }
    }
}

// ================= layer-2 aggregation of y2 (8 bytes/edge) ====================
__global__ void k_agg2(float* __restrict__ out) {
    int v = (blockIdx.x * blockDim.x + threadIdx.x) >> 5;
    int lane = threadIdx.x & 31;
    if (v >= N_NODES) return;
    int deg = g_deg[v]; if (deg > CAP) deg = CAP;
    const int* bkt = g_bkt + (size_t)v * CAP;
    float a0 = 0.f, a1 = 0.f;
    for (int e = lane; e < deg; e += 32) {
        int s = bkt[e];
        float2 y = ((const float2*)g_y2)[s];
        a0 += y.x; a1 += y.y;
    }
#pragma unroll
    for (int o = 16; o > 0; o >>= 1) {
        a0 += __shfl_xor_sync(0xFFFFFFFFu, a0, o);
        a1 += __shfl_xor_sync(0xFFFFFFFFu, a1, o);
    }
    if (lane == 0) {
        float inv = 1.0f / fmaxf((float)deg, 1.0f);
        out[v * 2 + 0] += a0 * inv;
        out[v * 2 + 1] += a1 * inv;
    }
}

// ================= launch ======================================================
extern "C" void kernel_launch(void* const* d_in, const int* in_sizes, int n_in,
                              void* d_out, int out_size)
{
    const float* x    = (const float*)d_in[0];
    const int*   ei   = (const int*)d_in[1];
    const float* W1l  = (const float*)d_in[2];
    const float* W1r  = (const float*)d_in[3];
    const float* b1   = (const float*)d_in[4];
    const float* W2l  = (const float*)d_in[5];
    const float* W2r  = (const float*)d_in[6];
    const float* b2   = (const float*)d_in[7];
    float* out = (float*)d_out;

    const int DSMEM = 3 * TBYTES;   // 55296 B
    cudaFuncSetAttribute(k_gemm_mma, cudaFuncAttributeMaxDynamicSharedMemorySize, DSMEM);

    const int XBLOCKS = (N_NODES * 128 / 2 + 255) / 256;   // 12500
    k_zero_prep<<<196 + 128 + XBLOCKS, 256>>>(W1l, W1r, x);
    k_bin<<<PREP_BLOCKS, 256>>>(ei);
    k_agg1<<<(N_NODES * 32 + 255) / 256, 256>>>();
    k_gemm_mma<<<(N_NODES + 127) / 128, 256, DSMEM>>>(b1, W2l, W2r, b2, out);
    k_agg2<<<(N_NODES * 32 + 255) / 256, 256>>>(out);
}

// round 16
// speedup vs baseline: 3.3709x; 1.2034x over previous
#include <cuda_runtime.h>
#include <cuda_bf16.h>
#include <cuda_fp16.h>
#include <cstdint>

#define N_NODES 50000
#define N_EDGES 800000
#define D 128
#define CAP 128            // bucket capacity per dst (Poisson(16): overflow ~1e-60)

// ================= scratch =====================================================
__device__ __align__(16) int    g_deg[N_NODES];
__device__ __align__(16) int    g_bkt[(size_t)N_NODES * CAP];  // src buckets
__device__ __align__(16) float  g_y2[(size_t)N_NODES * 2];     // h @ W2_l^T
__device__ __align__(16) __half g_ahi[(size_t)N_NODES * 256];  // A=[agg|x] fp16
__device__ __align__(16) __half g_w1h[128 * 256];              // [Wl|Wr] fp16

// ================= helpers =====================================================
__device__ __forceinline__ uint32_t smem_u32(const void* p) {
    uint32_t a;
    asm("{ .reg .u64 t; cvta.to.shared.u64 t, %1; cvt.u32.u64 %0, t; }"
        : "=r"(a) : "l"(p));
    return a;
}

__device__ __forceinline__ void ldmx4(uint32_t* r, uint32_t addr) {
    asm volatile("ldmatrix.sync.aligned.m8n8.x4.shared.b16 {%0,%1,%2,%3}, [%4];"
        : "=r"(r[0]), "=r"(r[1]), "=r"(r[2]), "=r"(r[3]) : "r"(addr));
}

__device__ __forceinline__ void mma16816(float* d, const uint32_t* a,
                                         uint32_t b0, uint32_t b1) {
    asm volatile("mma.sync.aligned.m16n8k16.row.col.f32.f16.f16.f32 "
        "{%0,%1,%2,%3}, {%4,%5,%6,%7}, {%8,%9}, {%0,%1,%2,%3};"
        : "+f"(d[0]), "+f"(d[1]), "+f"(d[2]), "+f"(d[3])
        : "r"(a[0]), "r"(a[1]), "r"(a[2]), "r"(a[3]), "r"(b0), "r"(b1));
}

// ================= prep: zero deg + W fp16 + x fp16 (merged) ===================
// grid: [0,196) zero g_deg; [196,324) W rows; [324, 324+12500) x convert
__global__ void k_zero_prep(const float* __restrict__ Wl, const float* __restrict__ Wr,
                            const float* __restrict__ x) {
    int b = blockIdx.x;
    if (b < 196) {
        int i = b * 256 + threadIdx.x;
        if (i < N_NODES) g_deg[i] = 0;
    } else if (b < 324) {
        int j = b - 196;                // 0..127
        int k = threadIdx.x;            // 0..255
        float v = (k < 128) ? Wl[j * 128 + k] : Wr[j * 128 + (k - 128)];
        g_w1h[j * 256 + k] = __float2half(v);
    } else {
        long long p = (long long)(b - 324) * 256 + threadIdx.x;
        long long idx = p * 2;
        if (idx < (long long)N_NODES * 128) {
            int node = (int)(idx >> 7);
            int col = (int)(idx & 127);
            float v0 = x[(size_t)node * 128 + col];
            float v1 = x[(size_t)node * 128 + col + 1];
            __half2* ph = (__half2*)(g_ahi + (size_t)node * 256 + 128 + col);
            *ph = __halves2half2(__float2half(v0), __float2half(v1));
        }
    }
}

// ================= single-pass binning: 8 edges per thread =====================
#define EPT 8
#define PREP_BLOCKS ((N_EDGES + 256 * EPT - 1) / (256 * EPT))   // 391

__global__ void k_bin(const int* __restrict__ ei) {
    int t0 = (blockIdx.x * blockDim.x + threadIdx.x) * EPT;
    int srcs[EPT], dsts[EPT];
#pragma unroll
    for (int i = 0; i < EPT; ++i) {
        int e = t0 + i;
        srcs[i] = (e < N_EDGES) ? ei[e] : -1;
        dsts[i] = (e < N_EDGES) ? ei[N_EDGES + e] : -1;
    }
#pragma unroll
    for (int i = 0; i < EPT; ++i) {
        if ((unsigned)dsts[i] < (unsigned)N_NODES && (unsigned)srcs[i] < (unsigned)N_NODES) {
            int slot = atomicAdd(&g_deg[dsts[i]], 1);
            if (slot < CAP) g_bkt[(size_t)dsts[i] * CAP + slot] = srcs[i];
        }
    }
}

// ================= layer-1 aggregation: gather fp16 x (256B/row) ===============
__global__ void k_agg1() {
    int w = (blockIdx.x * blockDim.x + threadIdx.x) >> 5;
    int lane = threadIdx.x & 31;
    if (w >= N_NODES) return;
    int deg = g_deg[w]; if (deg > CAP) deg = CAP;
    const int* bkt = g_bkt + (size_t)w * CAP;
    float a0 = 0.f, a1 = 0.f, a2 = 0.f, a3 = 0.f;
    int e = 0;
    for (; e + 4 <= deg; e += 4) {
        int s0 = bkt[e], s1 = bkt[e + 1], s2 = bkt[e + 2], s3 = bkt[e + 3];
        uint2 u0 = ((const uint2*)(g_ahi + (size_t)s0 * 256 + 128))[lane];
        uint2 u1 = ((const uint2*)(g_ahi + (size_t)s1 * 256 + 128))[lane];
        uint2 u2 = ((const uint2*)(g_ahi + (size_t)s2 * 256 + 128))[lane];
        uint2 u3 = ((const uint2*)(g_ahi + (size_t)s3 * 256 + 128))[lane];
#pragma unroll
        for (int q = 0; q < 4; ++q) {
            uint2 u = (q == 0) ? u0 : (q == 1) ? u1 : (q == 2) ? u2 : u3;
            float2 f0 = __half22float2(*(__half2*)&u.x);
            float2 f1 = __half22float2(*(__half2*)&u.y);
            a0 += f0.x; a1 += f0.y; a2 += f1.x; a3 += f1.y;
        }
    }
    for (; e < deg; ++e) {
        int s = bkt[e];
        uint2 u = ((const uint2*)(g_ahi + (size_t)s * 256 + 128))[lane];
        float2 f0 = __half22float2(*(__half2*)&u.x);
        float2 f1 = __half22float2(*(__half2*)&u.y);
        a0 += f0.x; a1 += f0.y; a2 += f1.x; a3 += f1.y;
    }
    float inv = 1.0f / fmaxf((float)deg, 1.0f);
    *(__half2*)(g_ahi + (size_t)w * 256 + lane * 4) =
        __halves2half2(__float2half(a0 * inv), __float2half(a1 * inv));
    *(__half2*)(g_ahi + (size_t)w * 256 + lane * 4 + 2) =
        __halves2half2(__float2half(a2 * inv), __float2half(a3 * inv));
}

// ================= fused layer1 GEMM (fp16 mma, 1-pass) + layer2 self ==========
#define TSTRIDE_B 144         // bytes per smem tile row (64 fp16 data + pad)
#define TBYTES  (128 * TSTRIDE_B)     // 18432 per tile

__global__ void __launch_bounds__(256, 2) k_gemm_mma(
    const float* __restrict__ b1g,
    const float* __restrict__ W2l, const float* __restrict__ W2r,
    const float* __restrict__ b2,
    float* __restrict__ out)
{
    extern __shared__ char dynsm[];
    char* sAhi = dynsm;
    char* sBh  = dynsm + TBYTES;
    __shared__ float s_b1[128];
    __shared__ float s_w2[4][128];
    __shared__ float s_part[2][128][4];   // cross-warp-column epilogue combine

    const int tid = threadIdx.x;
    const int w = tid >> 5;
    const int lane = tid & 31;
    const int wm = w >> 1;          // 0..3  (m32 row group)
    const int wn = w & 1;           // 0..1  (n64 col group)
    const int m0 = blockIdx.x * 128;

    if (tid < 128) {
        s_b1[tid] = b1g[tid];
        s_w2[0][tid] = W2l[tid];
        s_w2[1][tid] = W2l[128 + tid];
        s_w2[2][tid] = W2r[tid];
        s_w2[3][tid] = W2r[128 + tid];
    }

    const uint32_t uAhi = smem_u32(sAhi);
    const uint32_t uBh = smem_u32(sBh);

    float acc[2][8][4];     // [am(m16)][n8 tile][frag]
#pragma unroll
    for (int am = 0; am < 2; ++am)
#pragma unroll
        for (int j = 0; j < 8; ++j)
#pragma unroll
            for (int q = 0; q < 4; ++q) acc[am][j][q] = 0.f;

    const int srow = tid >> 1;          // staging row 0..127
    const int shalf = tid & 1;          // 0/1 -> 64B half of 128B chunk row

    for (int c = 0; c < 4; ++c) {
        if (c) __syncthreads();         // previous chunk's mma reads done
        // ---- stage A + B: pure 16B copies (pre-converted fp16)
        {
            int node = m0 + srow;
            bool valid = node < N_NODES;
            const char* pah = (const char*)g_ahi + (size_t)(valid ? node : 0) * 512
                              + c * 128 + shalf * 64;
            char* dh = sAhi + srow * TSTRIDE_B + shalf * 64;
            const uint4 z = make_uint4(0, 0, 0, 0);
#pragma unroll
            for (int i = 0; i < 4; ++i)
                *(uint4*)(dh + i * 16) = valid ? *(const uint4*)(pah + i * 16) : z;
            const char* pb = (const char*)g_w1h + srow * 512 + c * 128 + shalf * 64;
            char* db = sBh + srow * TSTRIDE_B + shalf * 64;
#pragma unroll
            for (int i = 0; i < 4; ++i)
                *(uint4*)(db + i * 16) = *(const uint4*)(pb + i * 16);
        }
        __syncthreads();

        // ---- compute: 4 k16-steps per chunk; warp tile m32 x n64; single pass
        const uint32_t lrow = lane & 15, lhalf = lane >> 4;
#pragma unroll
        for (int ks = 0; ks < 4; ++ks) {
            const uint32_t koff = (ks * 16 + lhalf * 8) * 2;   // bytes
            uint32_t ah[2][4];
            ldmx4(ah[0], uAhi + (wm * 32 + lrow) * TSTRIDE_B + koff);
            ldmx4(ah[1], uAhi + (wm * 32 + 16 + lrow) * TSTRIDE_B + koff);
#pragma unroll
            for (int nt = 0; nt < 4; ++nt) {
                uint32_t bh[4];
                ldmx4(bh, uBh + (wn * 64 + nt * 16 + lrow) * TSTRIDE_B + koff);
#pragma unroll
                for (int am = 0; am < 2; ++am) {
                    mma16816(acc[am][2 * nt],     ah[am], bh[0], bh[2]);
                    mma16816(acc[am][2 * nt + 1], ah[am], bh[1], bh[3]);
                }
            }
        }
    }

    // ---- epilogue: bias + relu + partial layer2 dots over this warp's n64
    const int quad = lane >> 2;     // 0..7
    const int qt = lane & 3;        // 0..3
    float p[2][2][4];               // [am][row half 0:+0 1:+8][output]
#pragma unroll
    for (int am = 0; am < 2; ++am)
#pragma unroll
        for (int rh = 0; rh < 2; ++rh)
#pragma unroll
            for (int o = 0; o < 4; ++o) p[am][rh][o] = 0.f;

#pragma unroll
    for (int j = 0; j < 8; ++j) {
        int col0 = wn * 64 + j * 8 + qt * 2;
#pragma unroll
        for (int am = 0; am < 2; ++am) {
            float h00 = fmaxf(acc[am][j][0] + s_b1[col0],     0.f);
            float h01 = fmaxf(acc[am][j][1] + s_b1[col0 + 1], 0.f);
            float h10 = fmaxf(acc[am][j][2] + s_b1[col0],     0.f);
            float h11 = fmaxf(acc[am][j][3] + s_b1[col0 + 1], 0.f);
#pragma unroll
            for (int o = 0; o < 4; ++o) {
                p[am][0][o] += h00 * s_w2[o][col0] + h01 * s_w2[o][col0 + 1];
                p[am][1][o] += h10 * s_w2[o][col0] + h11 * s_w2[o][col0 + 1];
            }
        }
    }
#pragma unroll
    for (int m = 1; m <= 2; m <<= 1)
#pragma unroll
        for (int am = 0; am < 2; ++am)
#pragma unroll
            for (int rh = 0; rh < 2; ++rh)
#pragma unroll
                for (int o = 0; o < 4; ++o)
                    p[am][rh][o] += __shfl_xor_sync(0xFFFFFFFFu, p[am][rh][o], m);

    if (qt == 0) {
#pragma unroll
        for (int am = 0; am < 2; ++am)
#pragma unroll
            for (int rh = 0; rh < 2; ++rh) {
                int rl = wm * 32 + am * 16 + rh * 8 + quad;
#pragma unroll
                for (int o = 0; o < 4; ++o) s_part[wn][rl][o] = p[am][rh][o];
            }
    }
    __syncthreads();

    if (tid < 128) {
        int row = m0 + tid;
        if (row < N_NODES) {
            float v0 = s_part[0][tid][0] + s_part[1][tid][0];
            float v1 = s_part[0][tid][1] + s_part[1][tid][1];
            float v2 = s_part[0][tid][2] + s_part[1][tid][2];
            float v3 = s_part[0][tid][3] + s_part[1][tid][3];
            *(float2*)(g_y2 + (size_t)row * 2) = make_float2(v0, v1);
            *(float2*)(out + (size_t)row * 2) = make_float2(v2 + b2[0], v3 + b2[1]);
        }
    }
}

// ================= layer-2 aggregation of y2 (8 bytes/edge) ====================
__global__ void k_agg2(float* __restrict__ out) {
    int v = (blockIdx.x * blockDim.x + threadIdx.x) >> 5;
    int lane = threadIdx.x & 31;
    if (v >= N_NODES) return;
    int deg = g_deg[v]; if (deg > CAP) deg = CAP;
    const int* bkt = g_bkt + (size_t)v * CAP;
    float a0 = 0.f, a1 = 0.f;
    for (int e = lane; e < deg; e += 32) {
        int s = bkt[e];
        float2 y = ((const float2*)g_y2)[s];
        a0 += y.x; a1 += y.y;
    }
#pragma unroll
    for (int o = 16; o > 0; o >>= 1) {
        a0 += __shfl_xor_sync(0xFFFFFFFFu, a0, o);
        a1 += __shfl_xor_sync(0xFFFFFFFFu, a1, o);
    }
    if (lane == 0) {
        float inv = 1.0f / fmaxf((float)deg, 1.0f);
        out[v * 2 + 0] += a0 * inv;
        out[v * 2 + 1] += a1 * inv;
    }
}

// ================= launch ======================================================
extern "C" void kernel_launch(void* const* d_in, const int* in_sizes, int n_in,
                              void* d_out, int out_size)
{
    const float* x    = (const float*)d_in[0];
    const int*   ei   = (const int*)d_in[1];
    const float* W1l  = (const float*)d_in[2];
    const float* W1r  = (const float*)d_in[3];
    const float* b1   = (const float*)d_in[4];
    const float* W2l  = (const float*)d_in[5];
    const float* W2r  = (const float*)d_in[6];
    const float* b2   = (const float*)d_in[7];
    float* out = (float*)d_out;

    const int DSMEM = 2 * TBYTES;   // 36864 B
    cudaFuncSetAttribute(k_gemm_mma, cudaFuncAttributeMaxDynamicSharedMemorySize, DSMEM);

    const int XBLOCKS = (N_NODES * 128 / 2 + 255) / 256;   // 12500
    k_zero_prep<<<196 + 128 + XBLOCKS, 256>>>(W1l, W1r, x);
    k_bin<<<PREP_BLOCKS, 256>>>(ei);
    k_agg1<<<(N_NODES * 32 + 255) / 256, 256>>>();
    k_gemm_mma<<<(N_NODES + 127) / 128, 256, DSMEM>>>(b1, W2l, W2r, b2, out);
    k_agg2<<<(N_NODES * 32 + 255) / 256, 256>>>(out);
}